// round 12
// baseline (speedup 1.0000x reference)
#include <cuda_runtime.h>
#include <cuda_fp16.h>
#include <cstdint>

#define BN  4
#define C   64
#define HH  64
#define WWD 64
#define HWN 4096
#define EPSV 1e-5f

// Scratch (static device globals; no allocation at runtime)
__device__ float g_conv[2][BN][C][HWN];      // dwconv+leaky outputs
__device__ float g_attp[2][2][BN][C][HWN];   // UNNORMALIZED attention partials [split][ob]
__device__ float g_lp[2][2][BN][HWN];        // softmax-denominator partials [split][ob]
__device__ float g_stats[2][BN][C][2];       // per-channel sum, sumsq
__device__ float g_coef[2][BN][C][2];        // per-channel alpha, beta (groupnorm)
__device__ __half g_qT[2][BN][HWN][64];      // Q transposed [hw][d], pre-scaled by 0.125
__device__ __half g_kT[2][BN][HWN][64];      // K transposed [hw][d]
__device__ __half g_vb[2][BN][64][HWN];      // V [d][hw]

__device__ __forceinline__ int refl(int i, int n) {
    if (i < 0) i = -i;
    if (i >= n) i = 2*n - 2 - i;
    return i;
}

__device__ __forceinline__ float rna(float x) {
    uint32_t r;
    asm("cvt.rna.tf32.f32 %0, %1;" : "=r"(r) : "f"(x));
    return __uint_as_float(r);
}

__device__ __forceinline__ void mma_tf32(float c[4],
                                         uint32_t a0, uint32_t a1, uint32_t a2, uint32_t a3,
                                         uint32_t b0, uint32_t b1) {
    asm volatile(
        "mma.sync.aligned.m16n8k8.row.col.f32.tf32.tf32.f32 "
        "{%0,%1,%2,%3}, {%4,%5,%6,%7}, {%8,%9}, {%0,%1,%2,%3};"
        : "+f"(c[0]), "+f"(c[1]), "+f"(c[2]), "+f"(c[3])
        : "r"(a0), "r"(a1), "r"(a2), "r"(a3), "r"(b0), "r"(b1));
}

__device__ __forceinline__ void mma_f16(float c[4],
                                        uint32_t a0, uint32_t a1, uint32_t a2, uint32_t a3,
                                        uint32_t b0, uint32_t b1) {
    asm volatile(
        "mma.sync.aligned.m16n8k16.row.col.f32.f16.f16.f32 "
        "{%0,%1,%2,%3}, {%4,%5,%6,%7}, {%8,%9}, {%0,%1,%2,%3};"
        : "+f"(c[0]), "+f"(c[1]), "+f"(c[2]), "+f"(c[3])
        : "r"(a0), "r"(a1), "r"(a2), "r"(a3), "r"(b0), "r"(b1));
}

__device__ __forceinline__ void ldsm4(uint32_t& r0, uint32_t& r1, uint32_t& r2, uint32_t& r3,
                                      uint32_t addr) {
    asm volatile("ldmatrix.sync.aligned.m8n8.x4.shared.b16 {%0,%1,%2,%3}, [%4];"
                 : "=r"(r0), "=r"(r1), "=r"(r2), "=r"(r3) : "r"(addr));
}

__device__ __forceinline__ uint32_t pack_f16(float lo, float hi) {
    uint32_t r;
    asm("cvt.rn.f16x2.f32 %0, %1, %2;" : "=r"(r) : "f"(hi), "f"(lo));
    return r;
}

__device__ __forceinline__ uint32_t exp2_f16x2(uint32_t y) {
    uint32_t r;
    asm("ex2.approx.f16x2 %0, %1;" : "=r"(r) : "r"(y));
    return r;
}

// ---------------------------------------------------------------------------
// Kernel 1: depthwise conv, both branches, + per-channel stats. grid (C, BN)
// ---------------------------------------------------------------------------
__global__ void __launch_bounds__(256) dwconv_kernel(
        const float* __restrict__ inp,
        const float* __restrict__ w3, const float* __restrict__ b3,
        const float* __restrict__ w5, const float* __restrict__ b5) {
    __shared__ float t[68*68];
    int c = blockIdx.x, b = blockIdx.y;
    int tid = threadIdx.x;
    const float* src = inp + (b*C + c)*HWN;

    for (int idx = tid; idx < 68*68; idx += 256) {
        int r = idx / 68, col = idx - r*68;
        t[idx] = src[refl(r-2, HH)*WWD + refl(col-2, WWD)];
    }
    float w3r[9], w5r[25];
    #pragma unroll
    for (int k = 0; k < 9;  k++) w3r[k] = __ldg(w3 + c*9  + k);
    #pragma unroll
    for (int k = 0; k < 25; k++) w5r[k] = __ldg(w5 + c*25 + k);
    float bb3 = __ldg(b3 + c), bb5 = __ldg(b5 + c);
    __syncthreads();

    float s0 = 0.f, ss0 = 0.f, s1 = 0.f, ss1 = 0.f;
    #pragma unroll 4
    for (int k = 0; k < 16; k++) {
        int hw = tid + 256*k;
        int i = hw >> 6, j = hw & 63;
        const float* ce = &t[(i+2)*68 + (j+2)];
        float a3 = bb3;
        #pragma unroll
        for (int a = 0; a < 3; a++)
            #pragma unroll
            for (int q = 0; q < 3; q++)
                a3 += w3r[a*3+q] * ce[(a-1)*68 + (q-1)];
        float a5 = bb5;
        #pragma unroll
        for (int a = 0; a < 5; a++)
            #pragma unroll
            for (int q = 0; q < 5; q++)
                a5 += w5r[a*5+q] * ce[(a-2)*68 + (q-2)];
        float y0 = a3 > 0.f ? a3 : 0.01f*a3;
        float y1 = a5 > 0.f ? a5 : 0.01f*a5;
        g_conv[0][b][c][hw] = y0;
        g_conv[1][b][c][hw] = y1;
        s0 += y0; ss0 += y0*y0; s1 += y1; ss1 += y1*y1;
    }
    __syncthreads();
    t[tid] = s0; t[256+tid] = ss0; t[512+tid] = s1; t[768+tid] = ss1;
    __syncthreads();
    for (int st = 128; st > 0; st >>= 1) {
        if (tid < st) {
            t[tid]     += t[tid+st];     t[256+tid] += t[256+tid+st];
            t[512+tid] += t[512+tid+st]; t[768+tid] += t[768+tid+st];
        }
        __syncthreads();
    }
    if (tid == 0) {
        g_stats[0][b][c][0] = t[0];   g_stats[0][b][c][1] = t[256];
        g_stats[1][b][c][0] = t[512]; g_stats[1][b][c][1] = t[768];
    }
}

// ---------------------------------------------------------------------------
// Kernel 2: fold GroupNorm stats into per-channel alpha/beta. 1 block, 512 thr
// ---------------------------------------------------------------------------
__global__ void coef_kernel(const float* __restrict__ gwA, const float* __restrict__ gbA,
                            const float* __restrict__ gwB, const float* __restrict__ gbB) {
    int idx = threadIdx.x;
    int br = idx >> 8, b = (idx >> 6) & 3, c = idx & 63;
    int g0 = c & ~3;
    float sum = 0.f, ssum = 0.f;
    #pragma unroll
    for (int k = 0; k < 4; k++) {
        sum  += g_stats[br][b][g0+k][0];
        ssum += g_stats[br][b][g0+k][1];
    }
    float mean = sum * (1.f/16384.f);
    float var  = ssum * (1.f/16384.f) - mean*mean;
    float rs   = rsqrtf(var + EPSV);
    float gw = br ? __ldg(gwB + c) : __ldg(gwA + c);
    float gb = br ? __ldg(gbB + c) : __ldg(gbA + c);
    float alpha = rs * gw;
    g_coef[br][b][c][0] = alpha;
    g_coef[br][b][c][1] = gb - mean * alpha;
}

// ---------------------------------------------------------------------------
// Kernel 3: qkv 1x1 conv (tf32 mma), GN fused into X staging.
// Q -> g_qT fp16 [hw][d] scaled 0.125; K -> g_kT fp16 [hw][d]; V -> g_vb fp16 [d][hw]
// grid (64, BN, 2), block 384, dyn smem 70656
// ---------------------------------------------------------------------------
#define WPAD 68
#define XPAD 72

__global__ void __launch_bounds__(384) qkv_kernel(const float* __restrict__ wA,
                                                  const float* __restrict__ wB) {
    extern __shared__ float qsm[];
    float* Ws = qsm;              // [192][WPAD]
    float* Xs = qsm + 192*WPAD;   // [64][XPAD]

    int br = blockIdx.z, b = blockIdx.y;
    int hw0 = blockIdx.x * 64;
    int tid = threadIdx.x;
    const float* W  = br ? wB : wA;
    const float* Xc = &g_conv[br][b][0][0];

    #pragma unroll
    for (int i = 0; i < 8; i++) {
        int idx = tid + i*384;
        int row = idx >> 4, c4 = (idx & 15)*4;
        uint32_t d = (uint32_t)__cvta_generic_to_shared(Ws + row*WPAD + c4);
        asm volatile("cp.async.cg.shared.global [%0], [%1], 16;" :: "r"(d), "l"(W + row*64 + c4));
    }
    asm volatile("cp.async.commit_group;");
    for (int i = tid; i < 1024; i += 384) {
        int row = i >> 4, c4 = (i & 15)*4;
        float4 v = *(const float4*)&Xc[row*HWN + hw0 + c4];
        float a  = g_coef[br][b][row][0];
        float be = g_coef[br][b][row][1];
        float4 r;
        r.x = rna(a*v.x + be); r.y = rna(a*v.y + be);
        r.z = rna(a*v.z + be); r.w = rna(a*v.w + be);
        *(float4*)&Xs[row*XPAD + c4] = r;
    }
    asm volatile("cp.async.wait_group 0;");
    __syncthreads();

    int w    = tid >> 5;
    int lane = tid & 31;
    int g    = lane >> 2, tig = lane & 3;
    int out0 = w * 16;

    uint32_t aw[8][4];
    #pragma unroll
    for (int t = 0; t < 8; t++) {
        aw[t][0] = __float_as_uint(rna(Ws[(out0+g  )*WPAD + 8*t + tig    ]));
        aw[t][1] = __float_as_uint(rna(Ws[(out0+g+8)*WPAD + 8*t + tig    ]));
        aw[t][2] = __float_as_uint(rna(Ws[(out0+g  )*WPAD + 8*t + tig + 4]));
        aw[t][3] = __float_as_uint(rna(Ws[(out0+g+8)*WPAD + 8*t + tig + 4]));
    }

    float s[8][4] = {};
    #pragma unroll
    for (int t = 0; t < 8; t++)
        #pragma unroll
        for (int j = 0; j < 8; j++) {
            uint32_t b0 = __float_as_uint(Xs[(8*t+tig  )*XPAD + 8*j + g]);
            uint32_t b1 = __float_as_uint(Xs[(8*t+tig+4)*XPAD + 8*j + g]);
            mma_tf32(s[j], aw[t][0], aw[t][1], aw[t][2], aw[t][3], b0, b1);
        }

    if (out0 < 64) {                  // Q -> g_qT [hw][d] fp16, pre-scaled
        __half* qT = &g_qT[br][b][0][0];
        int o0 = out0 + g, o1 = o0 + 8;
        #pragma unroll
        for (int j = 0; j < 8; j++) {
            int hwj = hw0 + 8*j + 2*tig;
            qT[(hwj  )*64 + o0] = __float2half(s[j][0]*0.125f);
            qT[(hwj+1)*64 + o0] = __float2half(s[j][1]*0.125f);
            qT[(hwj  )*64 + o1] = __float2half(s[j][2]*0.125f);
            qT[(hwj+1)*64 + o1] = __float2half(s[j][3]*0.125f);
        }
    } else if (out0 < 128) {          // K -> g_kT [hw][d] fp16
        __half* kT = &g_kT[br][b][0][0];
        int o0 = out0 - 64 + g, o1 = o0 + 8;
        #pragma unroll
        for (int j = 0; j < 8; j++) {
            int hwj = hw0 + 8*j + 2*tig;
            kT[(hwj  )*64 + o0] = __float2half(s[j][0]);
            kT[(hwj+1)*64 + o0] = __float2half(s[j][1]);
            kT[(hwj  )*64 + o1] = __float2half(s[j][2]);
            kT[(hwj+1)*64 + o1] = __float2half(s[j][3]);
        }
    } else {                          // V -> g_vb [d][hw] fp16 packed
        int d0 = out0 - 128 + g, d1 = d0 + 8;
        #pragma unroll
        for (int j = 0; j < 8; j++) {
            int hwj = hw0 + 8*j + 2*tig;
            *(uint32_t*)&g_vb[br][b][d0][hwj] = pack_f16(s[j][0], s[j][1]);
            *(uint32_t*)&g_vb[br][b][d1][hwj] = pack_f16(s[j][2], s[j][3]);
        }
    }
}

// ---------------------------------------------------------------------------
// Kernel 4: flash attention, fp16 mma + ldmatrix, warp-M=32, SPLIT-K over keys.
// Each CTA: 256-q tile x 32 key tiles (split 0: kt 0-31, split 1: kt 32-63).
// Emits UNNORMALIZED O partial + l partial. grid (32, BN, 2): x = qt*2+split.
// 256 CTAs -> 2 CTAs/SM -> 16 warps/SM latency hiding with warp-M=32 reuse.
// block 256, dyn smem 73728.
// ---------------------------------------------------------------------------
#define KVP 144   // bytes per smem row (72 halves)
#define L2E 1.4426950408889634f

__global__ void __launch_bounds__(256, 2) attn_kernel() {
    extern __shared__ char smc[];
    char* KTc = smc;                  // [2][64][KVP]
    char* Vc  = smc + 2*64*KVP;       // [2][64][KVP]
    char* Pc  = Vc  + 2*64*KVP;       // [8][32][KVP]

    int qt    = blockIdx.x >> 1;
    int split = blockIdx.x & 1;
    int b  = blockIdx.y;
    int ob = blockIdx.z;
    int kt0 = split * 32;
    const __half* qTg = &g_qT[ob^1][b][0][0];
    const char* kg = (const char*)&g_kT[ob][b][0][0];
    const char* vg = (const char*)&g_vb[ob][b][0][0];

    int tid  = threadIdx.x;
    int w    = tid >> 5;
    int lane = tid & 31;
    int g    = lane >> 2, tig = lane & 3;
    char* Pw = Pc + w*32*KVP;
    int qw = 32*w;

    // cp.async staging: K tile 64x128B, V tile 64x128B; 2 chunks each per thread
    int row8 = tid >> 3, ch = tid & 7;
    const char* ksg = kg + row8*128  + ch*16 + kt0*8192;
    const char* vsg = vg + row8*8192 + ch*16 + kt0*128;
    uint32_t kss = (uint32_t)__cvta_generic_to_shared(KTc) + row8*KVP + ch*16;
    uint32_t vss = (uint32_t)__cvta_generic_to_shared(Vc)  + row8*KVP + ch*16;
    const uint32_t KVBUF = 64*KVP;

    // Q A-fragments (fp16 pairs, pre-scaled): 4 k16-steps x 2 row-blocks
    uint32_t qa[4][2][4];
    #pragma unroll
    for (int r = 0; r < 2; r++) {
        int r0 = (qt*256 + qw + 16*r + g)*64;
        int r1 = r0 + 8*64;
        #pragma unroll
        for (int t = 0; t < 4; t++) {
            qa[t][r][0] = *(const uint32_t*)&qTg[r0 + 16*t + 2*tig    ];
            qa[t][r][1] = *(const uint32_t*)&qTg[r1 + 16*t + 2*tig    ];
            qa[t][r][2] = *(const uint32_t*)&qTg[r0 + 16*t + 2*tig + 8];
            qa[t][r][3] = *(const uint32_t*)&qTg[r1 + 16*t + 2*tig + 8];
        }
    }

    // ldmatrix lane addressing
    int p  = lane & 7;
    int q4 = lane >> 3;
    uint32_t rowpart = (uint32_t)((8*(q4 >> 1) + p)*KVP + 16*(q4 & 1));
    uint32_t kaddr0 = (uint32_t)__cvta_generic_to_shared(KTc) + rowpart;
    uint32_t vaddr0 = (uint32_t)__cvta_generic_to_shared(Vc)  + rowpart;
    uint32_t paddr0 = (uint32_t)__cvta_generic_to_shared(Pw)
                    + (uint32_t)((8*(q4 & 1) + p)*KVP + 16*(q4 >> 1));

    // constant ones B-fragment for l accumulators
    uint32_t bone = (lane < 4) ? 0x3C003C00u : 0u;

    // prefetch first tile
    #pragma unroll
    for (int i = 0; i < 2; i++) {
        asm volatile("cp.async.cg.shared.global [%0], [%1], 16;"
                     :: "r"(kss + (uint32_t)(i*32*KVP)), "l"(ksg + i*4096));
        asm volatile("cp.async.cg.shared.global [%0], [%1], 16;"
                     :: "r"(vss + (uint32_t)(i*32*KVP)), "l"(vsg + i*262144));
    }
    asm volatile("cp.async.commit_group;");

    float o[2][8][4] = {};
    float o9[2][4] = {};   // l accumulators per row-block

    for (int kt = 0; kt < 32; kt++) {
        int buf = kt & 1;
        asm volatile("cp.async.wait_group 0;");
        __syncthreads();

        if (kt + 1 < 32) {
            uint32_t boff = (buf ^ 1) * KVBUF;
            const char* kn = ksg + (kt+1)*8192;
            const char* vn = vsg + (kt+1)*128;
            #pragma unroll
            for (int i = 0; i < 2; i++) {
                asm volatile("cp.async.cg.shared.global [%0], [%1], 16;"
                             :: "r"(kss + boff + (uint32_t)(i*32*KVP)), "l"(kn + i*4096));
                asm volatile("cp.async.cg.shared.global [%0], [%1], 16;"
                             :: "r"(vss + boff + (uint32_t)(i*32*KVP)), "l"(vn + i*262144));
            }
            asm volatile("cp.async.commit_group;");
        }

        uint32_t kb = kaddr0 + buf*KVBUF;
        uint32_t vb = vaddr0 + buf*KVBUF;

        // ---- S = Q K^T : 4 k16-steps; b-frags shared across 2 row-blocks ----
        float s[2][8][4] = {};
        #pragma unroll
        for (int t = 0; t < 4; t++) {
            uint32_t b0[8], b1[8];
            #pragma unroll
            for (int n = 0; n < 4; n++)
                ldsm4(b0[2*n], b1[2*n], b0[2*n+1], b1[2*n+1],
                      kb + (uint32_t)(n*16*KVP) + 32u*t);
            #pragma unroll
            for (int r = 0; r < 2; r++)
                #pragma unroll
                for (int j = 0; j < 8; j++)
                    mma_f16(s[r][j], qa[t][r][0], qa[t][r][1], qa[t][r][2], qa[t][r][3],
                            b0[j], b1[j]);
        }

        // ---- p = 2^((s-2)*log2e) via f16x2 MUFU; output IS the P fragment ----
        #pragma unroll
        for (int r = 0; r < 2; r++)
            #pragma unroll
            for (int j = 0; j < 8; j++) {
                float y0 = fmaf(s[r][j][0], L2E, -2.f*L2E);
                float y1 = fmaf(s[r][j][1], L2E, -2.f*L2E);
                float y2 = fmaf(s[r][j][2], L2E, -2.f*L2E);
                float y3 = fmaf(s[r][j][3], L2E, -2.f*L2E);
                uint32_t pp0 = exp2_f16x2(pack_f16(y0, y1));
                uint32_t pp1 = exp2_f16x2(pack_f16(y2, y3));
                *(uint32_t*)(Pw + (16*r+g  )*KVP + (8*j + 2*tig)*2) = pp0;
                *(uint32_t*)(Pw + (16*r+g+8)*KVP + (8*j + 2*tig)*2) = pp1;
            }
        __syncwarp();

        // ---- O += P V (+ l += P 1) : 4 k16-steps; V b-frags shared ----
        #pragma unroll
        for (int t = 0; t < 4; t++) {
            uint32_t b0[8], b1[8];
            #pragma unroll
            for (int n = 0; n < 4; n++)
                ldsm4(b0[2*n], b1[2*n], b0[2*n+1], b1[2*n+1],
                      vb + (uint32_t)(n*16*KVP) + 32u*t);
            uint32_t pa[2][4];
            #pragma unroll
            for (int r = 0; r < 2; r++)
                ldsm4(pa[r][0], pa[r][1], pa[r][2], pa[r][3],
                      paddr0 + (uint32_t)(16*r*KVP) + 32u*t);
            #pragma unroll
            for (int r = 0; r < 2; r++) {
                #pragma unroll
                for (int j = 0; j < 8; j++)
                    mma_f16(o[r][j], pa[r][0], pa[r][1], pa[r][2], pa[r][3],
                            b0[j], b1[j]);
                mma_f16(o9[r], pa[r][0], pa[r][1], pa[r][2], pa[r][3], bone, bone);
            }
        }
        __syncwarp();   // O-phase P reads done before next iter's P stores
    }

    // ---- epilogue: store UNNORMALIZED partials + l partials ----
    float* dst = &g_attp[split][ob][b][0][0];
    float* lp  = &g_lp[split][ob][b][0];
    #pragma unroll
    for (int r = 0; r < 2; r++) {
        int qb = qt*256 + qw + 16*r;
        if (tig == 0) {
            lp[qb + g    ] = o9[r][0];
            lp[qb + g + 8] = o9[r][2];
        }
        #pragma unroll
        for (int j = 0; j < 8; j++) {
            int d0 = 8*j + 2*tig;
            dst[(d0  )*HWN + qb + g    ] = o[r][j][0];
            dst[(d0+1)*HWN + qb + g    ] = o[r][j][1];
            dst[(d0  )*HWN + qb + g + 8] = o[r][j][2];
            dst[(d0+1)*HWN + qb + g + 8] = o[r][j][3];
        }
    }
}

// ---------------------------------------------------------------------------
// Kernel 5: out 1x1 conv (tf32 mma) + split-K combine + bias + residual + concat
// X = (O0 + O1) / (l0 + l1), computed during staging.
// ---------------------------------------------------------------------------
__global__ void __launch_bounds__(128) outproj_kernel(
        const float* __restrict__ wA, const float* __restrict__ bA,
        const float* __restrict__ wB, const float* __restrict__ bB,
        float* __restrict__ out) {
    __shared__ float Ws[64*WPAD];
    __shared__ float Xs[64*XPAD];

    int ob = blockIdx.z, b = blockIdx.y;
    int hw0 = blockIdx.x * 64;
    int tid = threadIdx.x;
    const float* W    = ob ? wB : wA;
    const float* bias = ob ? bB : bA;
    const float* A0   = &g_attp[0][ob][b][0][0];
    const float* A1   = &g_attp[1][ob][b][0][0];
    const float* L0   = &g_lp[0][ob][b][0];
    const float* L1   = &g_lp[1][ob][b][0];
    const float* conv = &g_conv[ob][b][0][0];

    #pragma unroll
    for (int i = 0; i < 8; i++) {
        int idx = tid + i*128;
        int row = idx >> 4, c4 = (idx & 15)*4;
        uint32_t dW = (uint32_t)__cvta_generic_to_shared(Ws + row*WPAD + c4);
        asm volatile("cp.async.cg.shared.global [%0], [%1], 16;" :: "r"(dW), "l"(W + row*64 + c4));
    }
    asm volatile("cp.async.commit_group;");
    // combine split-K partials during X staging
    for (int i = tid; i < 1024; i += 128) {
        int row = i >> 4, c4 = (i & 15)*4;
        float4 v0 = *(const float4*)&A0[row*HWN + hw0 + c4];
        float4 v1 = *(const float4*)&A1[row*HWN + hw0 + c4];
        float4 p0 = *(const float4*)&L0[hw0 + c4];
        float4 p1 = *(const float4*)&L1[hw0 + c4];
        float4 r;
        r.x = rna((v0.x + v1.x) / (p0.x + p1.x));
        r.y = rna((v0.y + v1.y) / (p0.y + p1.y));
        r.z = rna((v0.z + v1.z) / (p0.z + p1.z));
        r.w = rna((v0.w + v1.w) / (p0.w + p1.w));
        *(float4*)&Xs[row*XPAD + c4] = r;
    }
    asm volatile("cp.async.wait_group 0;");
    __syncthreads();

    int w    = tid >> 5;
    int lane = tid & 31;
    int g    = lane >> 2, tig = lane & 3;
    int out0 = w * 16;

    uint32_t aw[8][4];
    #pragma unroll
    for (int t = 0; t < 8; t++) {
        aw[t][0] = __float_as_uint(rna(Ws[(out0+g  )*WPAD + 8*t + tig    ]));
        aw[t][1] = __float_as_uint(rna(Ws[(out0+g+8)*WPAD + 8*t + tig    ]));
        aw[t][2] = __float_as_uint(rna(Ws[(out0+g  )*WPAD + 8*t + tig + 4]));
        aw[t][3] = __float_as_uint(rna(Ws[(out0+g+8)*WPAD + 8*t + tig + 4]));
    }

    float s[8][4] = {};
    #pragma unroll
    for (int t = 0; t < 8; t++)
        #pragma unroll
        for (int j = 0; j < 8; j++) {
            uint32_t b0 = __float_as_uint(Xs[(8*t+tig  )*XPAD + 8*j + g]);
            uint32_t b1 = __float_as_uint(Xs[(8*t+tig+4)*XPAD + 8*j + g]);
            mma_tf32(s[j], aw[t][0], aw[t][1], aw[t][2], aw[t][3], b0, b1);
        }

    int o0 = out0 + g, o1 = out0 + g + 8;
    float bi0 = __ldg(bias + o0), bi1 = __ldg(bias + o1);
    float a0 = g_coef[ob][b][o0][0], be0 = g_coef[ob][b][o0][1];
    float a1 = g_coef[ob][b][o1][0], be1 = g_coef[ob][b][o1][1];
    float* dst = out + (b*128 + ob*64)*HWN;
    #pragma unroll
    for (int j = 0; j < 8; j++) {
        int hwj = hw0 + 8*j + 2*tig;
        float2 c0 = *(const float2*)&conv[o0*HWN + hwj];
        float2 c1 = *(const float2*)&conv[o1*HWN + hwj];
        *(float2*)&dst[o0*HWN + hwj] =
            make_float2(s[j][0] + bi0 + (a0*c0.x + be0), s[j][1] + bi0 + (a0*c0.y + be0));
        *(float2*)&dst[o1*HWN + hwj] =
            make_float2(s[j][2] + bi1 + (a1*c1.x + be1), s[j][3] + bi1 + (a1*c1.y + be1));
    }
}

// ---------------------------------------------------------------------------
extern "C" void kernel_launch(void* const* d_in, const int* in_sizes, int n_in,
                              void* d_out, int out_size) {
    const float* inputs = (const float*)d_in[0];
    const float* dw1_w  = (const float*)d_in[1];
    const float* dw1_b  = (const float*)d_in[2];
    const float* dw2_w  = (const float*)d_in[3];
    const float* dw2_b  = (const float*)d_in[4];
    const float* gnA_w  = (const float*)d_in[5];
    const float* gnA_b  = (const float*)d_in[6];
    const float* gnB_w  = (const float*)d_in[7];
    const float* gnB_b  = (const float*)d_in[8];
    const float* qkvA_w = (const float*)d_in[9];
    const float* qkvB_w = (const float*)d_in[10];
    const float* outA_w = (const float*)d_in[11];
    const float* outA_b = (const float*)d_in[12];
    const float* outB_w = (const float*)d_in[13];
    const float* outB_b = (const float*)d_in[14];
    float* out = (float*)d_out;

    cudaFuncSetAttribute(attn_kernel, cudaFuncAttributeMaxDynamicSharedMemorySize, 73728);
    cudaFuncSetAttribute(qkv_kernel,  cudaFuncAttributeMaxDynamicSharedMemorySize, 70656);

    dwconv_kernel <<<dim3(64, BN),    256>>>(inputs, dw1_w, dw1_b, dw2_w, dw2_b);
    coef_kernel   <<<1, 512>>>(gnA_w, gnA_b, gnB_w, gnB_b);
    qkv_kernel    <<<dim3(64, BN, 2), 384, 70656>>>(qkvA_w, qkvB_w);
    attn_kernel   <<<dim3(32, BN, 2), 256, 73728>>>();
    outproj_kernel<<<dim3(64, BN, 2), 128>>>(outA_w, outA_b, outB_w, outB_b, out);
}

// round 13
// speedup vs baseline: 1.2582x; 1.2582x over previous
#include <cuda_runtime.h>
#include <cuda_fp16.h>
#include <cstdint>

#define BN  4
#define C   64
#define HH  64
#define WWD 64
#define HWN 4096
#define EPSV 1e-5f

// Scratch (static device globals; no allocation at runtime)
__device__ float g_conv[2][BN][C][HWN];      // dwconv+leaky outputs
__device__ float g_att[2][BN][C][HWN];       // attention outputs (by OUT branch)
__device__ float g_stats[2][BN][C][2];       // per-channel sum, sumsq
__device__ float g_coef[2][BN][C][2];        // per-channel alpha, beta (groupnorm)
__device__ __half g_qT[2][BN][HWN][64];      // Q transposed [hw][d], pre-scaled by 0.125
__device__ __half g_kT[2][BN][HWN][64];      // K transposed [hw][d]
__device__ __half g_vb[2][BN][64][HWN];      // V [d][hw]

__device__ __forceinline__ int refl(int i, int n) {
    if (i < 0) i = -i;
    if (i >= n) i = 2*n - 2 - i;
    return i;
}

__device__ __forceinline__ float rna(float x) {
    uint32_t r;
    asm("cvt.rna.tf32.f32 %0, %1;" : "=r"(r) : "f"(x));
    return __uint_as_float(r);
}

__device__ __forceinline__ void mma_tf32(float c[4],
                                         uint32_t a0, uint32_t a1, uint32_t a2, uint32_t a3,
                                         uint32_t b0, uint32_t b1) {
    asm volatile(
        "mma.sync.aligned.m16n8k8.row.col.f32.tf32.tf32.f32 "
        "{%0,%1,%2,%3}, {%4,%5,%6,%7}, {%8,%9}, {%0,%1,%2,%3};"
        : "+f"(c[0]), "+f"(c[1]), "+f"(c[2]), "+f"(c[3])
        : "r"(a0), "r"(a1), "r"(a2), "r"(a3), "r"(b0), "r"(b1));
}

__device__ __forceinline__ void mma_f16(float c[4],
                                        uint32_t a0, uint32_t a1, uint32_t a2, uint32_t a3,
                                        uint32_t b0, uint32_t b1) {
    asm volatile(
        "mma.sync.aligned.m16n8k16.row.col.f32.f16.f16.f32 "
        "{%0,%1,%2,%3}, {%4,%5,%6,%7}, {%8,%9}, {%0,%1,%2,%3};"
        : "+f"(c[0]), "+f"(c[1]), "+f"(c[2]), "+f"(c[3])
        : "r"(a0), "r"(a1), "r"(a2), "r"(a3), "r"(b0), "r"(b1));
}

__device__ __forceinline__ void ldsm4(uint32_t& r0, uint32_t& r1, uint32_t& r2, uint32_t& r3,
                                      uint32_t addr) {
    asm volatile("ldmatrix.sync.aligned.m8n8.x4.shared.b16 {%0,%1,%2,%3}, [%4];"
                 : "=r"(r0), "=r"(r1), "=r"(r2), "=r"(r3) : "r"(addr));
}

__device__ __forceinline__ uint32_t pack_f16(float lo, float hi) {
    uint32_t r;
    asm("cvt.rn.f16x2.f32 %0, %1, %2;" : "=r"(r) : "f"(hi), "f"(lo));
    return r;
}

__device__ __forceinline__ uint32_t exp2_f16x2(uint32_t y) {
    uint32_t r;
    asm("ex2.approx.f16x2 %0, %1;" : "=r"(r) : "r"(y));
    return r;
}

// ---------------------------------------------------------------------------
// Kernel 1: depthwise conv, both branches, + per-channel stats. grid (C, BN)
// ---------------------------------------------------------------------------
__global__ void __launch_bounds__(256) dwconv_kernel(
        const float* __restrict__ inp,
        const float* __restrict__ w3, const float* __restrict__ b3,
        const float* __restrict__ w5, const float* __restrict__ b5) {
    __shared__ float t[68*68];
    int c = blockIdx.x, b = blockIdx.y;
    int tid = threadIdx.x;
    const float* src = inp + (b*C + c)*HWN;

    for (int idx = tid; idx < 68*68; idx += 256) {
        int r = idx / 68, col = idx - r*68;
        t[idx] = src[refl(r-2, HH)*WWD + refl(col-2, WWD)];
    }
    float w3r[9], w5r[25];
    #pragma unroll
    for (int k = 0; k < 9;  k++) w3r[k] = __ldg(w3 + c*9  + k);
    #pragma unroll
    for (int k = 0; k < 25; k++) w5r[k] = __ldg(w5 + c*25 + k);
    float bb3 = __ldg(b3 + c), bb5 = __ldg(b5 + c);
    __syncthreads();

    float s0 = 0.f, ss0 = 0.f, s1 = 0.f, ss1 = 0.f;
    #pragma unroll 4
    for (int k = 0; k < 16; k++) {
        int hw = tid + 256*k;
        int i = hw >> 6, j = hw & 63;
        const float* ce = &t[(i+2)*68 + (j+2)];
        float a3 = bb3;
        #pragma unroll
        for (int a = 0; a < 3; a++)
            #pragma unroll
            for (int q = 0; q < 3; q++)
                a3 += w3r[a*3+q] * ce[(a-1)*68 + (q-1)];
        float a5 = bb5;
        #pragma unroll
        for (int a = 0; a < 5; a++)
            #pragma unroll
            for (int q = 0; q < 5; q++)
                a5 += w5r[a*5+q] * ce[(a-2)*68 + (q-2)];
        float y0 = a3 > 0.f ? a3 : 0.01f*a3;
        float y1 = a5 > 0.f ? a5 : 0.01f*a5;
        g_conv[0][b][c][hw] = y0;
        g_conv[1][b][c][hw] = y1;
        s0 += y0; ss0 += y0*y0; s1 += y1; ss1 += y1*y1;
    }
    __syncthreads();
    t[tid] = s0; t[256+tid] = ss0; t[512+tid] = s1; t[768+tid] = ss1;
    __syncthreads();
    for (int st = 128; st > 0; st >>= 1) {
        if (tid < st) {
            t[tid]     += t[tid+st];     t[256+tid] += t[256+tid+st];
            t[512+tid] += t[512+tid+st]; t[768+tid] += t[768+tid+st];
        }
        __syncthreads();
    }
    if (tid == 0) {
        g_stats[0][b][c][0] = t[0];   g_stats[0][b][c][1] = t[256];
        g_stats[1][b][c][0] = t[512]; g_stats[1][b][c][1] = t[768];
    }
}

// ---------------------------------------------------------------------------
// Kernel 2: fold GroupNorm stats into per-channel alpha/beta. 1 block, 512 thr
// ---------------------------------------------------------------------------
__global__ void coef_kernel(const float* __restrict__ gwA, const float* __restrict__ gbA,
                            const float* __restrict__ gwB, const float* __restrict__ gbB) {
    int idx = threadIdx.x;
    int br = idx >> 8, b = (idx >> 6) & 3, c = idx & 63;
    int g0 = c & ~3;
    float sum = 0.f, ssum = 0.f;
    #pragma unroll
    for (int k = 0; k < 4; k++) {
        sum  += g_stats[br][b][g0+k][0];
        ssum += g_stats[br][b][g0+k][1];
    }
    float mean = sum * (1.f/16384.f);
    float var  = ssum * (1.f/16384.f) - mean*mean;
    float rs   = rsqrtf(var + EPSV);
    float gw = br ? __ldg(gwB + c) : __ldg(gwA + c);
    float gb = br ? __ldg(gbB + c) : __ldg(gbA + c);
    float alpha = rs * gw;
    g_coef[br][b][c][0] = alpha;
    g_coef[br][b][c][1] = gb - mean * alpha;
}

// ---------------------------------------------------------------------------
// Kernel 3: qkv 1x1 conv (tf32 mma), GN fused into X staging.
// Q -> g_qT fp16 [hw][d] scaled 0.125; K -> g_kT fp16 [hw][d]; V -> g_vb fp16 [d][hw]
// grid (64, BN, 2), block 384, dyn smem 70656
// ---------------------------------------------------------------------------
#define WPAD 68
#define XPAD 72

__global__ void __launch_bounds__(384) qkv_kernel(const float* __restrict__ wA,
                                                  const float* __restrict__ wB) {
    extern __shared__ float qsm[];
    float* Ws = qsm;              // [192][WPAD]
    float* Xs = qsm + 192*WPAD;   // [64][XPAD]

    int br = blockIdx.z, b = blockIdx.y;
    int hw0 = blockIdx.x * 64;
    int tid = threadIdx.x;
    const float* W  = br ? wB : wA;
    const float* Xc = &g_conv[br][b][0][0];

    #pragma unroll
    for (int i = 0; i < 8; i++) {
        int idx = tid + i*384;
        int row = idx >> 4, c4 = (idx & 15)*4;
        uint32_t d = (uint32_t)__cvta_generic_to_shared(Ws + row*WPAD + c4);
        asm volatile("cp.async.cg.shared.global [%0], [%1], 16;" :: "r"(d), "l"(W + row*64 + c4));
    }
    asm volatile("cp.async.commit_group;");
    for (int i = tid; i < 1024; i += 384) {
        int row = i >> 4, c4 = (i & 15)*4;
        float4 v = *(const float4*)&Xc[row*HWN + hw0 + c4];
        float a  = g_coef[br][b][row][0];
        float be = g_coef[br][b][row][1];
        float4 r;
        r.x = rna(a*v.x + be); r.y = rna(a*v.y + be);
        r.z = rna(a*v.z + be); r.w = rna(a*v.w + be);
        *(float4*)&Xs[row*XPAD + c4] = r;
    }
    asm volatile("cp.async.wait_group 0;");
    __syncthreads();

    int w    = tid >> 5;
    int lane = tid & 31;
    int g    = lane >> 2, tig = lane & 3;
    int out0 = w * 16;

    uint32_t aw[8][4];
    #pragma unroll
    for (int t = 0; t < 8; t++) {
        aw[t][0] = __float_as_uint(rna(Ws[(out0+g  )*WPAD + 8*t + tig    ]));
        aw[t][1] = __float_as_uint(rna(Ws[(out0+g+8)*WPAD + 8*t + tig    ]));
        aw[t][2] = __float_as_uint(rna(Ws[(out0+g  )*WPAD + 8*t + tig + 4]));
        aw[t][3] = __float_as_uint(rna(Ws[(out0+g+8)*WPAD + 8*t + tig + 4]));
    }

    float s[8][4] = {};
    #pragma unroll
    for (int t = 0; t < 8; t++)
        #pragma unroll
        for (int j = 0; j < 8; j++) {
            uint32_t b0 = __float_as_uint(Xs[(8*t+tig  )*XPAD + 8*j + g]);
            uint32_t b1 = __float_as_uint(Xs[(8*t+tig+4)*XPAD + 8*j + g]);
            mma_tf32(s[j], aw[t][0], aw[t][1], aw[t][2], aw[t][3], b0, b1);
        }

    if (out0 < 64) {                  // Q -> g_qT [hw][d] fp16, pre-scaled
        __half* qT = &g_qT[br][b][0][0];
        int o0 = out0 + g, o1 = o0 + 8;
        #pragma unroll
        for (int j = 0; j < 8; j++) {
            int hwj = hw0 + 8*j + 2*tig;
            qT[(hwj  )*64 + o0] = __float2half(s[j][0]*0.125f);
            qT[(hwj+1)*64 + o0] = __float2half(s[j][1]*0.125f);
            qT[(hwj  )*64 + o1] = __float2half(s[j][2]*0.125f);
            qT[(hwj+1)*64 + o1] = __float2half(s[j][3]*0.125f);
        }
    } else if (out0 < 128) {          // K -> g_kT [hw][d] fp16
        __half* kT = &g_kT[br][b][0][0];
        int o0 = out0 - 64 + g, o1 = o0 + 8;
        #pragma unroll
        for (int j = 0; j < 8; j++) {
            int hwj = hw0 + 8*j + 2*tig;
            kT[(hwj  )*64 + o0] = __float2half(s[j][0]);
            kT[(hwj+1)*64 + o0] = __float2half(s[j][1]);
            kT[(hwj  )*64 + o1] = __float2half(s[j][2]);
            kT[(hwj+1)*64 + o1] = __float2half(s[j][3]);
        }
    } else {                          // V -> g_vb [d][hw] fp16 packed
        int d0 = out0 - 128 + g, d1 = d0 + 8;
        #pragma unroll
        for (int j = 0; j < 8; j++) {
            int hwj = hw0 + 8*j + 2*tig;
            *(uint32_t*)&g_vb[br][b][d0][hwj] = pack_f16(s[j][0], s[j][1]);
            *(uint32_t*)&g_vb[br][b][d1][hwj] = pack_f16(s[j][2], s[j][3]);
        }
    }
}

// ---------------------------------------------------------------------------
// Kernel 4: flash attention, fp16 mma + ldmatrix, warp-M=32, SMALL CTA:
// block 128 (4 warps x 32 q-rows = 128-q tile), grid (32, BN, 2) = 256 CTAs
// -> 2 CTAs/SM (regs ~209 legal: 2*128*209 < 64K). Independent CTAs
// interleave their S/softmax/O phases on the shared pipes.
// dyn smem 55296.
// ---------------------------------------------------------------------------
#define KVP 144   // bytes per smem row (72 halves)
#define L2E 1.4426950408889634f

__global__ void __launch_bounds__(128, 2) attn_kernel() {
    extern __shared__ char smc[];
    char* KTc = smc;                  // [2][64][KVP]
    char* Vc  = smc + 2*64*KVP;       // [2][64][KVP]
    char* Pc  = Vc  + 2*64*KVP;       // [4][32][KVP]

    int qt = blockIdx.x;
    int b  = blockIdx.y;
    int ob = blockIdx.z;
    const __half* qTg = &g_qT[ob^1][b][0][0];
    const char* kg = (const char*)&g_kT[ob][b][0][0];
    const char* vg = (const char*)&g_vb[ob][b][0][0];

    int tid  = threadIdx.x;
    int w    = tid >> 5;
    int lane = tid & 31;
    int g    = lane >> 2, tig = lane & 3;
    char* Pw = Pc + w*32*KVP;
    int qw = 32*w;

    // cp.async staging: 128 threads, 16B chunks; 4 passes cover 64 rows (128B/row)
    int row16 = tid >> 3, ch = tid & 7;      // row16: 0..15, ch: 0..7
    const char* ksg = kg + row16*128  + ch*16;   // +kt*8192;  +i*2048 (16 rows)
    const char* vsg = vg + row16*8192 + ch*16;   // +kt*128;   +i*131072
    uint32_t kss = (uint32_t)__cvta_generic_to_shared(KTc) + row16*KVP + ch*16;
    uint32_t vss = (uint32_t)__cvta_generic_to_shared(Vc)  + row16*KVP + ch*16;
    const uint32_t KVBUF = 64*KVP;

    // Q A-fragments (fp16 pairs, pre-scaled): 4 k16-steps x 2 row-blocks
    uint32_t qa[4][2][4];
    #pragma unroll
    for (int r = 0; r < 2; r++) {
        int r0 = (qt*128 + qw + 16*r + g)*64;
        int r1 = r0 + 8*64;
        #pragma unroll
        for (int t = 0; t < 4; t++) {
            qa[t][r][0] = *(const uint32_t*)&qTg[r0 + 16*t + 2*tig    ];
            qa[t][r][1] = *(const uint32_t*)&qTg[r1 + 16*t + 2*tig    ];
            qa[t][r][2] = *(const uint32_t*)&qTg[r0 + 16*t + 2*tig + 8];
            qa[t][r][3] = *(const uint32_t*)&qTg[r1 + 16*t + 2*tig + 8];
        }
    }

    // ldmatrix lane addressing
    int p  = lane & 7;
    int q4 = lane >> 3;
    uint32_t rowpart = (uint32_t)((8*(q4 >> 1) + p)*KVP + 16*(q4 & 1));
    uint32_t kaddr0 = (uint32_t)__cvta_generic_to_shared(KTc) + rowpart;
    uint32_t vaddr0 = (uint32_t)__cvta_generic_to_shared(Vc)  + rowpart;
    uint32_t paddr0 = (uint32_t)__cvta_generic_to_shared(Pw)
                    + (uint32_t)((8*(q4 & 1) + p)*KVP + 16*(q4 >> 1));

    // constant ones B-fragment for l accumulators
    uint32_t bone = (lane < 4) ? 0x3C003C00u : 0u;

    // prefetch kt=0
    #pragma unroll
    for (int i = 0; i < 4; i++) {
        asm volatile("cp.async.cg.shared.global [%0], [%1], 16;"
                     :: "r"(kss + (uint32_t)(i*16*KVP)), "l"(ksg + i*2048));
        asm volatile("cp.async.cg.shared.global [%0], [%1], 16;"
                     :: "r"(vss + (uint32_t)(i*16*KVP)), "l"(vsg + i*131072));
    }
    asm volatile("cp.async.commit_group;");

    float o[2][8][4] = {};
    float o9[2][4] = {};   // l accumulators per row-block

    for (int kt = 0; kt < 64; kt++) {
        int buf = kt & 1;
        asm volatile("cp.async.wait_group 0;");
        __syncthreads();

        if (kt + 1 < 64) {
            uint32_t boff = (buf ^ 1) * KVBUF;
            const char* kn = ksg + (kt+1)*8192;
            const char* vn = vsg + (kt+1)*128;
            #pragma unroll
            for (int i = 0; i < 4; i++) {
                asm volatile("cp.async.cg.shared.global [%0], [%1], 16;"
                             :: "r"(kss + boff + (uint32_t)(i*16*KVP)), "l"(kn + i*2048));
                asm volatile("cp.async.cg.shared.global [%0], [%1], 16;"
                             :: "r"(vss + boff + (uint32_t)(i*16*KVP)), "l"(vn + i*131072));
            }
            asm volatile("cp.async.commit_group;");
        }

        uint32_t kb = kaddr0 + buf*KVBUF;
        uint32_t vb = vaddr0 + buf*KVBUF;

        // ---- S = Q K^T : 4 k16-steps; b-frags shared across 2 row-blocks ----
        float s[2][8][4] = {};
        #pragma unroll
        for (int t = 0; t < 4; t++) {
            uint32_t b0[8], b1[8];
            #pragma unroll
            for (int n = 0; n < 4; n++)
                ldsm4(b0[2*n], b1[2*n], b0[2*n+1], b1[2*n+1],
                      kb + (uint32_t)(n*16*KVP) + 32u*t);
            #pragma unroll
            for (int r = 0; r < 2; r++)
                #pragma unroll
                for (int j = 0; j < 8; j++)
                    mma_f16(s[r][j], qa[t][r][0], qa[t][r][1], qa[t][r][2], qa[t][r][3],
                            b0[j], b1[j]);
        }

        // ---- p = 2^((s-2)*log2e) via f16x2 MUFU; output IS the P fragment ----
        #pragma unroll
        for (int r = 0; r < 2; r++)
            #pragma unroll
            for (int j = 0; j < 8; j++) {
                float y0 = fmaf(s[r][j][0], L2E, -2.f*L2E);
                float y1 = fmaf(s[r][j][1], L2E, -2.f*L2E);
                float y2 = fmaf(s[r][j][2], L2E, -2.f*L2E);
                float y3 = fmaf(s[r][j][3], L2E, -2.f*L2E);
                uint32_t pp0 = exp2_f16x2(pack_f16(y0, y1));
                uint32_t pp1 = exp2_f16x2(pack_f16(y2, y3));
                *(uint32_t*)(Pw + (16*r+g  )*KVP + (8*j + 2*tig)*2) = pp0;
                *(uint32_t*)(Pw + (16*r+g+8)*KVP + (8*j + 2*tig)*2) = pp1;
            }
        __syncwarp();

        // ---- O += P V (+ l += P 1) : 4 k16-steps; V b-frags shared ----
        #pragma unroll
        for (int t = 0; t < 4; t++) {
            uint32_t b0[8], b1[8];
            #pragma unroll
            for (int n = 0; n < 4; n++)
                ldsm4(b0[2*n], b1[2*n], b0[2*n+1], b1[2*n+1],
                      vb + (uint32_t)(n*16*KVP) + 32u*t);
            uint32_t pa[2][4];
            #pragma unroll
            for (int r = 0; r < 2; r++)
                ldsm4(pa[r][0], pa[r][1], pa[r][2], pa[r][3],
                      paddr0 + (uint32_t)(16*r*KVP) + 32u*t);
            #pragma unroll
            for (int r = 0; r < 2; r++) {
                #pragma unroll
                for (int j = 0; j < 8; j++)
                    mma_f16(o[r][j], pa[r][0], pa[r][1], pa[r][2], pa[r][3],
                            b0[j], b1[j]);
                mma_f16(o9[r], pa[r][0], pa[r][1], pa[r][2], pa[r][3], bone, bone);
            }
        }
        __syncwarp();   // O-phase P reads done before next iter's P stores
    }

    // ---- epilogue: l in o9[r][0]/o9[r][2] of tig==0 lanes; broadcast ----
    float* dst = &g_att[ob][b][0][0];
    #pragma unroll
    for (int r = 0; r < 2; r++) {
        float l0 = __shfl_sync(0xffffffffu, o9[r][0], lane & ~3);
        float l1 = __shfl_sync(0xffffffffu, o9[r][2], lane & ~3);
        float il0 = 1.f / l0, il1 = 1.f / l1;
        int qb = qt*128 + qw + 16*r;
        #pragma unroll
        for (int j = 0; j < 8; j++) {
            int d0 = 8*j + 2*tig;
            dst[(d0  )*HWN + qb + g    ] = o[r][j][0]*il0;
            dst[(d0+1)*HWN + qb + g    ] = o[r][j][1]*il0;
            dst[(d0  )*HWN + qb + g + 8] = o[r][j][2]*il1;
            dst[(d0+1)*HWN + qb + g + 8] = o[r][j][3]*il1;
        }
    }
}

// ---------------------------------------------------------------------------
// Kernel 5: out 1x1 conv (tf32 mma) + bias + residual (inline GN) + concat
// ---------------------------------------------------------------------------
__global__ void __launch_bounds__(128) outproj_kernel(
        const float* __restrict__ wA, const float* __restrict__ bA,
        const float* __restrict__ wB, const float* __restrict__ bB,
        float* __restrict__ out) {
    __shared__ float Ws[64*WPAD];
    __shared__ float Xs[64*XPAD];

    int ob = blockIdx.z, b = blockIdx.y;
    int hw0 = blockIdx.x * 64;
    int tid = threadIdx.x;
    const float* W    = ob ? wB : wA;
    const float* bias = ob ? bB : bA;
    const float* X    = &g_att[ob][b][0][0];
    const float* conv = &g_conv[ob][b][0][0];

    #pragma unroll
    for (int i = 0; i < 8; i++) {
        int idx = tid + i*128;
        int row = idx >> 4, c4 = (idx & 15)*4;
        uint32_t dW = (uint32_t)__cvta_generic_to_shared(Ws + row*WPAD + c4);
        asm volatile("cp.async.cg.shared.global [%0], [%1], 16;" :: "r"(dW), "l"(W + row*64 + c4));
    }
    asm volatile("cp.async.commit_group;");
    for (int i = tid; i < 1024; i += 128) {
        int row = i >> 4, c4 = (i & 15)*4;
        float4 v = *(const float4*)&X[row*HWN + hw0 + c4];
        float4 r;
        r.x = rna(v.x); r.y = rna(v.y); r.z = rna(v.z); r.w = rna(v.w);
        *(float4*)&Xs[row*XPAD + c4] = r;
    }
    asm volatile("cp.async.wait_group 0;");
    __syncthreads();

    int w    = tid >> 5;
    int lane = tid & 31;
    int g    = lane >> 2, tig = lane & 3;
    int out0 = w * 16;

    uint32_t aw[8][4];
    #pragma unroll
    for (int t = 0; t < 8; t++) {
        aw[t][0] = __float_as_uint(rna(Ws[(out0+g  )*WPAD + 8*t + tig    ]));
        aw[t][1] = __float_as_uint(rna(Ws[(out0+g+8)*WPAD + 8*t + tig    ]));
        aw[t][2] = __float_as_uint(rna(Ws[(out0+g  )*WPAD + 8*t + tig + 4]));
        aw[t][3] = __float_as_uint(rna(Ws[(out0+g+8)*WPAD + 8*t + tig + 4]));
    }

    float s[8][4] = {};
    #pragma unroll
    for (int t = 0; t < 8; t++)
        #pragma unroll
        for (int j = 0; j < 8; j++) {
            uint32_t b0 = __float_as_uint(Xs[(8*t+tig  )*XPAD + 8*j + g]);
            uint32_t b1 = __float_as_uint(Xs[(8*t+tig+4)*XPAD + 8*j + g]);
            mma_tf32(s[j], aw[t][0], aw[t][1], aw[t][2], aw[t][3], b0, b1);
        }

    int o0 = out0 + g, o1 = out0 + g + 8;
    float bi0 = __ldg(bias + o0), bi1 = __ldg(bias + o1);
    float a0 = g_coef[ob][b][o0][0], be0 = g_coef[ob][b][o0][1];
    float a1 = g_coef[ob][b][o1][0], be1 = g_coef[ob][b][o1][1];
    float* dst = out + (b*128 + ob*64)*HWN;
    #pragma unroll
    for (int j = 0; j < 8; j++) {
        int hwj = hw0 + 8*j + 2*tig;
        float2 c0 = *(const float2*)&conv[o0*HWN + hwj];
        float2 c1 = *(const float2*)&conv[o1*HWN + hwj];
        *(float2*)&dst[o0*HWN + hwj] =
            make_float2(s[j][0] + bi0 + (a0*c0.x + be0), s[j][1] + bi0 + (a0*c0.y + be0));
        *(float2*)&dst[o1*HWN + hwj] =
            make_float2(s[j][2] + bi1 + (a1*c1.x + be1), s[j][3] + bi1 + (a1*c1.y + be1));
    }
}

// ---------------------------------------------------------------------------
extern "C" void kernel_launch(void* const* d_in, const int* in_sizes, int n_in,
                              void* d_out, int out_size) {
    const float* inputs = (const float*)d_in[0];
    const float* dw1_w  = (const float*)d_in[1];
    const float* dw1_b  = (const float*)d_in[2];
    const float* dw2_w  = (const float*)d_in[3];
    const float* dw2_b  = (const float*)d_in[4];
    const float* gnA_w  = (const float*)d_in[5];
    const float* gnA_b  = (const float*)d_in[6];
    const float* gnB_w  = (const float*)d_in[7];
    const float* gnB_b  = (const float*)d_in[8];
    const float* qkvA_w = (const float*)d_in[9];
    const float* qkvB_w = (const float*)d_in[10];
    const float* outA_w = (const float*)d_in[11];
    const float* outA_b = (const float*)d_in[12];
    const float* outB_w = (const float*)d_in[13];
    const float* outB_b = (const float*)d_in[14];
    float* out = (float*)d_out;

    cudaFuncSetAttribute(attn_kernel, cudaFuncAttributeMaxDynamicSharedMemorySize, 55296);
    cudaFuncSetAttribute(qkv_kernel,  cudaFuncAttributeMaxDynamicSharedMemorySize, 70656);

    dwconv_kernel <<<dim3(64, BN),    256>>>(inputs, dw1_w, dw1_b, dw2_w, dw2_b);
    coef_kernel   <<<1, 512>>>(gnA_w, gnA_b, gnB_w, gnB_b);
    qkv_kernel    <<<dim3(64, BN, 2), 384, 70656>>>(qkvA_w, qkvB_w);
    attn_kernel   <<<dim3(32, BN, 2), 128, 55296>>>();
    outproj_kernel<<<dim3(64, BN, 2), 128>>>(outA_w, outA_b, outB_w, outB_b, out);
}

// round 15
// speedup vs baseline: 1.3767x; 1.0941x over previous
#include <cuda_runtime.h>
#include <cuda_fp16.h>
#include <cstdint>

#define BN  4
#define C   64
#define HH  64
#define WWD 64
#define HWN 4096
#define EPSV 1e-5f

// Scratch (static device globals; no allocation at runtime)
__device__ float g_conv[2][BN][C][HWN];      // dwconv+leaky outputs
__device__ float g_att[2][BN][C][HWN];       // attention outputs (by OUT branch)
__device__ float g_stats[2][BN][C][2];       // per-channel sum, sumsq
__device__ float g_coef[2][BN][C][2];        // per-channel alpha, beta (groupnorm)
__device__ __half g_qT[2][BN][HWN][64];      // Q transposed [hw][d], pre-scaled by 0.125
__device__ __half g_kT[2][BN][HWN][64];      // K transposed [hw][d]
__device__ __half g_vb[2][BN][64][HWN];      // V [d][hw]

__device__ __forceinline__ int refl(int i, int n) {
    if (i < 0) i = -i;
    if (i >= n) i = 2*n - 2 - i;
    return i;
}

__device__ __forceinline__ float rna(float x) {
    uint32_t r;
    asm("cvt.rna.tf32.f32 %0, %1;" : "=r"(r) : "f"(x));
    return __uint_as_float(r);
}

__device__ __forceinline__ void mma_tf32(float c[4],
                                         uint32_t a0, uint32_t a1, uint32_t a2, uint32_t a3,
                                         uint32_t b0, uint32_t b1) {
    asm volatile(
        "mma.sync.aligned.m16n8k8.row.col.f32.tf32.tf32.f32 "
        "{%0,%1,%2,%3}, {%4,%5,%6,%7}, {%8,%9}, {%0,%1,%2,%3};"
        : "+f"(c[0]), "+f"(c[1]), "+f"(c[2]), "+f"(c[3])
        : "r"(a0), "r"(a1), "r"(a2), "r"(a3), "r"(b0), "r"(b1));
}

__device__ __forceinline__ void mma_f16(float c[4],
                                        uint32_t a0, uint32_t a1, uint32_t a2, uint32_t a3,
                                        uint32_t b0, uint32_t b1) {
    asm volatile(
        "mma.sync.aligned.m16n8k16.row.col.f32.f16.f16.f32 "
        "{%0,%1,%2,%3}, {%4,%5,%6,%7}, {%8,%9}, {%0,%1,%2,%3};"
        : "+f"(c[0]), "+f"(c[1]), "+f"(c[2]), "+f"(c[3])
        : "r"(a0), "r"(a1), "r"(a2), "r"(a3), "r"(b0), "r"(b1));
}

__device__ __forceinline__ void ldsm4(uint32_t& r0, uint32_t& r1, uint32_t& r2, uint32_t& r3,
                                      uint32_t addr) {
    asm volatile("ldmatrix.sync.aligned.m8n8.x4.shared.b16 {%0,%1,%2,%3}, [%4];"
                 : "=r"(r0), "=r"(r1), "=r"(r2), "=r"(r3) : "r"(addr));
}

__device__ __forceinline__ uint32_t pack_f16(float lo, float hi) {
    uint32_t r;
    asm("cvt.rn.f16x2.f32 %0, %1, %2;" : "=r"(r) : "f"(hi), "f"(lo));
    return r;
}

__device__ __forceinline__ uint32_t exp2_f16x2(uint32_t y) {
    uint32_t r;
    asm("ex2.approx.f16x2 %0, %1;" : "=r"(r) : "r"(y));
    return r;
}

// ---------------------------------------------------------------------------
// Kernel 1: depthwise conv, both branches, + per-channel stats. grid (C, BN)
// ---------------------------------------------------------------------------
__global__ void __launch_bounds__(256) dwconv_kernel(
        const float* __restrict__ inp,
        const float* __restrict__ w3, const float* __restrict__ b3,
        const float* __restrict__ w5, const float* __restrict__ b5) {
    __shared__ float t[68*68];
    int c = blockIdx.x, b = blockIdx.y;
    int tid = threadIdx.x;
    const float* src = inp + (b*C + c)*HWN;

    for (int idx = tid; idx < 68*68; idx += 256) {
        int r = idx / 68, col = idx - r*68;
        t[idx] = src[refl(r-2, HH)*WWD + refl(col-2, WWD)];
    }
    float w3r[9], w5r[25];
    #pragma unroll
    for (int k = 0; k < 9;  k++) w3r[k] = __ldg(w3 + c*9  + k);
    #pragma unroll
    for (int k = 0; k < 25; k++) w5r[k] = __ldg(w5 + c*25 + k);
    float bb3 = __ldg(b3 + c), bb5 = __ldg(b5 + c);
    __syncthreads();

    float s0 = 0.f, ss0 = 0.f, s1 = 0.f, ss1 = 0.f;
    #pragma unroll 4
    for (int k = 0; k < 16; k++) {
        int hw = tid + 256*k;
        int i = hw >> 6, j = hw & 63;
        const float* ce = &t[(i+2)*68 + (j+2)];
        float a3 = bb3;
        #pragma unroll
        for (int a = 0; a < 3; a++)
            #pragma unroll
            for (int q = 0; q < 3; q++)
                a3 += w3r[a*3+q] * ce[(a-1)*68 + (q-1)];
        float a5 = bb5;
        #pragma unroll
        for (int a = 0; a < 5; a++)
            #pragma unroll
            for (int q = 0; q < 5; q++)
                a5 += w5r[a*5+q] * ce[(a-2)*68 + (q-2)];
        float y0 = a3 > 0.f ? a3 : 0.01f*a3;
        float y1 = a5 > 0.f ? a5 : 0.01f*a5;
        g_conv[0][b][c][hw] = y0;
        g_conv[1][b][c][hw] = y1;
        s0 += y0; ss0 += y0*y0; s1 += y1; ss1 += y1*y1;
    }
    __syncthreads();
    t[tid] = s0; t[256+tid] = ss0; t[512+tid] = s1; t[768+tid] = ss1;
    __syncthreads();
    for (int st = 128; st > 0; st >>= 1) {
        if (tid < st) {
            t[tid]     += t[tid+st];     t[256+tid] += t[256+tid+st];
            t[512+tid] += t[512+tid+st]; t[768+tid] += t[768+tid+st];
        }
        __syncthreads();
    }
    if (tid == 0) {
        g_stats[0][b][c][0] = t[0];   g_stats[0][b][c][1] = t[256];
        g_stats[1][b][c][0] = t[512]; g_stats[1][b][c][1] = t[768];
    }
}

// ---------------------------------------------------------------------------
// Kernel 2: fold GroupNorm stats into per-channel alpha/beta. 1 block, 512 thr
// ---------------------------------------------------------------------------
__global__ void coef_kernel(const float* __restrict__ gwA, const float* __restrict__ gbA,
                            const float* __restrict__ gwB, const float* __restrict__ gbB) {
    int idx = threadIdx.x;
    int br = idx >> 8, b = (idx >> 6) & 3, c = idx & 63;
    int g0 = c & ~3;
    float sum = 0.f, ssum = 0.f;
    #pragma unroll
    for (int k = 0; k < 4; k++) {
        sum  += g_stats[br][b][g0+k][0];
        ssum += g_stats[br][b][g0+k][1];
    }
    float mean = sum * (1.f/16384.f);
    float var  = ssum * (1.f/16384.f) - mean*mean;
    float rs   = rsqrtf(var + EPSV);
    float gw = br ? __ldg(gwB + c) : __ldg(gwA + c);
    float gb = br ? __ldg(gbB + c) : __ldg(gbA + c);
    float alpha = rs * gw;
    g_coef[br][b][c][0] = alpha;
    g_coef[br][b][c][1] = gb - mean * alpha;
}

// ---------------------------------------------------------------------------
// Kernel 3: qkv 1x1 conv (tf32 mma), GN fused into X staging.
// Q -> g_qT fp16 [hw][d] scaled 0.125; K -> g_kT fp16 [hw][d]; V -> g_vb fp16 [d][hw]
// grid (64, BN, 2), block 384, dyn smem 70656
// ---------------------------------------------------------------------------
#define WPAD 68
#define XPAD 72

__global__ void __launch_bounds__(384) qkv_kernel(const float* __restrict__ wA,
                                                  const float* __restrict__ wB) {
    extern __shared__ float qsm[];
    float* Ws = qsm;              // [192][WPAD]
    float* Xs = qsm + 192*WPAD;   // [64][XPAD]

    int br = blockIdx.z, b = blockIdx.y;
    int hw0 = blockIdx.x * 64;
    int tid = threadIdx.x;
    const float* W  = br ? wB : wA;
    const float* Xc = &g_conv[br][b][0][0];

    #pragma unroll
    for (int i = 0; i < 8; i++) {
        int idx = tid + i*384;
        int row = idx >> 4, c4 = (idx & 15)*4;
        uint32_t d = (uint32_t)__cvta_generic_to_shared(Ws + row*WPAD + c4);
        asm volatile("cp.async.cg.shared.global [%0], [%1], 16;" :: "r"(d), "l"(W + row*64 + c4));
    }
    asm volatile("cp.async.commit_group;");
    for (int i = tid; i < 1024; i += 384) {
        int row = i >> 4, c4 = (i & 15)*4;
        float4 v = *(const float4*)&Xc[row*HWN + hw0 + c4];
        float a  = g_coef[br][b][row][0];
        float be = g_coef[br][b][row][1];
        float4 r;
        r.x = rna(a*v.x + be); r.y = rna(a*v.y + be);
        r.z = rna(a*v.z + be); r.w = rna(a*v.w + be);
        *(float4*)&Xs[row*XPAD + c4] = r;
    }
    asm volatile("cp.async.wait_group 0;");
    __syncthreads();

    int w    = tid >> 5;
    int lane = tid & 31;
    int g    = lane >> 2, tig = lane & 3;
    int out0 = w * 16;

    uint32_t aw[8][4];
    #pragma unroll
    for (int t = 0; t < 8; t++) {
        aw[t][0] = __float_as_uint(rna(Ws[(out0+g  )*WPAD + 8*t + tig    ]));
        aw[t][1] = __float_as_uint(rna(Ws[(out0+g+8)*WPAD + 8*t + tig    ]));
        aw[t][2] = __float_as_uint(rna(Ws[(out0+g  )*WPAD + 8*t + tig + 4]));
        aw[t][3] = __float_as_uint(rna(Ws[(out0+g+8)*WPAD + 8*t + tig + 4]));
    }

    float s[8][4] = {};
    #pragma unroll
    for (int t = 0; t < 8; t++)
        #pragma unroll
        for (int j = 0; j < 8; j++) {
            uint32_t b0 = __float_as_uint(Xs[(8*t+tig  )*XPAD + 8*j + g]);
            uint32_t b1 = __float_as_uint(Xs[(8*t+tig+4)*XPAD + 8*j + g]);
            mma_tf32(s[j], aw[t][0], aw[t][1], aw[t][2], aw[t][3], b0, b1);
        }

    if (out0 < 64) {                  // Q -> g_qT [hw][d] fp16, pre-scaled
        __half* qT = &g_qT[br][b][0][0];
        int o0 = out0 + g, o1 = o0 + 8;
        #pragma unroll
        for (int j = 0; j < 8; j++) {
            int hwj = hw0 + 8*j + 2*tig;
            qT[(hwj  )*64 + o0] = __float2half(s[j][0]*0.125f);
            qT[(hwj+1)*64 + o0] = __float2half(s[j][1]*0.125f);
            qT[(hwj  )*64 + o1] = __float2half(s[j][2]*0.125f);
            qT[(hwj+1)*64 + o1] = __float2half(s[j][3]*0.125f);
        }
    } else if (out0 < 128) {          // K -> g_kT [hw][d] fp16
        __half* kT = &g_kT[br][b][0][0];
        int o0 = out0 - 64 + g, o1 = o0 + 8;
        #pragma unroll
        for (int j = 0; j < 8; j++) {
            int hwj = hw0 + 8*j + 2*tig;
            kT[(hwj  )*64 + o0] = __float2half(s[j][0]);
            kT[(hwj+1)*64 + o0] = __float2half(s[j][1]);
            kT[(hwj  )*64 + o1] = __float2half(s[j][2]);
            kT[(hwj+1)*64 + o1] = __float2half(s[j][3]);
        }
    } else {                          // V -> g_vb [d][hw] fp16 packed
        int d0 = out0 - 128 + g, d1 = d0 + 8;
        #pragma unroll
        for (int j = 0; j < 8; j++) {
            int hwj = hw0 + 8*j + 2*tig;
            *(uint32_t*)&g_vb[br][b][d0][hwj] = pack_f16(s[j][0], s[j][1]);
            *(uint32_t*)&g_vb[br][b][d1][hwj] = pack_f16(s[j][2], s[j][3]);
        }
    }
}

// ---------------------------------------------------------------------------
// Kernel 4: flash attention, fp16 mma + ldmatrix, warp-M=32, small CTA,
// DIRECT C->A fragment reuse (fixed ordering): packed ex2.f16x2 outputs are
// the O-MMA A-fragments in PTX order A0=(g,klo) A1=(g+8,klo) A2=(g,khi)
// A3=(g+8,khi): pa[t] = {pp0(j=2t), pp1(j=2t), pp0(j=2t+1), pp1(j=2t+1)}.
// No P smem round-trip, no syncwarp.
// block 128 (4 warps x 32 q-rows), grid (32, BN, 2) = 256 CTAs, 2 CTAs/SM.
// dyn smem 46080.
// ---------------------------------------------------------------------------
#define KVP 144   // bytes per smem row (72 halves)
#define L2E 1.4426950408889634f

__global__ void __launch_bounds__(128, 2) attn_kernel() {
    extern __shared__ char smc[];
    char* KTc = smc;                  // [2][64][KVP]
    char* Vc  = smc + 2*64*KVP;       // [2][64][KVP]

    int qt = blockIdx.x;
    int b  = blockIdx.y;
    int ob = blockIdx.z;
    const __half* qTg = &g_qT[ob^1][b][0][0];
    const char* kg = (const char*)&g_kT[ob][b][0][0];
    const char* vg = (const char*)&g_vb[ob][b][0][0];

    int tid  = threadIdx.x;
    int w    = tid >> 5;
    int lane = tid & 31;
    int g    = lane >> 2, tig = lane & 3;
    int qw = 32*w;

    // cp.async staging: 128 threads, 16B chunks; 4 passes cover 64 rows (128B/row)
    int row16 = tid >> 3, ch = tid & 7;
    const char* ksg = kg + row16*128  + ch*16;   // +kt*8192;  +i*2048 (16 rows)
    const char* vsg = vg + row16*8192 + ch*16;   // +kt*128;   +i*131072
    uint32_t kss = (uint32_t)__cvta_generic_to_shared(KTc) + row16*KVP + ch*16;
    uint32_t vss = (uint32_t)__cvta_generic_to_shared(Vc)  + row16*KVP + ch*16;
    const uint32_t KVBUF = 64*KVP;

    // Q A-fragments (fp16 pairs, pre-scaled): 4 k16-steps x 2 row-blocks
    uint32_t qa[4][2][4];
    #pragma unroll
    for (int r = 0; r < 2; r++) {
        int r0 = (qt*128 + qw + 16*r + g)*64;
        int r1 = r0 + 8*64;
        #pragma unroll
        for (int t = 0; t < 4; t++) {
            qa[t][r][0] = *(const uint32_t*)&qTg[r0 + 16*t + 2*tig    ];
            qa[t][r][1] = *(const uint32_t*)&qTg[r1 + 16*t + 2*tig    ];
            qa[t][r][2] = *(const uint32_t*)&qTg[r0 + 16*t + 2*tig + 8];
            qa[t][r][3] = *(const uint32_t*)&qTg[r1 + 16*t + 2*tig + 8];
        }
    }

    // ldmatrix lane addressing
    int p  = lane & 7;
    int q4 = lane >> 3;
    uint32_t rowpart = (uint32_t)((8*(q4 >> 1) + p)*KVP + 16*(q4 & 1));
    uint32_t kaddr0 = (uint32_t)__cvta_generic_to_shared(KTc) + rowpart;
    uint32_t vaddr0 = (uint32_t)__cvta_generic_to_shared(Vc)  + rowpart;

    // constant ones B-fragment for l accumulators
    uint32_t bone = (lane < 4) ? 0x3C003C00u : 0u;

    // prefetch kt=0
    #pragma unroll
    for (int i = 0; i < 4; i++) {
        asm volatile("cp.async.cg.shared.global [%0], [%1], 16;"
                     :: "r"(kss + (uint32_t)(i*16*KVP)), "l"(ksg + i*2048));
        asm volatile("cp.async.cg.shared.global [%0], [%1], 16;"
                     :: "r"(vss + (uint32_t)(i*16*KVP)), "l"(vsg + i*131072));
    }
    asm volatile("cp.async.commit_group;");

    float o[2][8][4] = {};
    float o9[2][4] = {};   // l accumulators per row-block

    for (int kt = 0; kt < 64; kt++) {
        int buf = kt & 1;
        asm volatile("cp.async.wait_group 0;");
        __syncthreads();

        if (kt + 1 < 64) {
            uint32_t boff = (buf ^ 1) * KVBUF;
            const char* kn = ksg + (kt+1)*8192;
            const char* vn = vsg + (kt+1)*128;
            #pragma unroll
            for (int i = 0; i < 4; i++) {
                asm volatile("cp.async.cg.shared.global [%0], [%1], 16;"
                             :: "r"(kss + boff + (uint32_t)(i*16*KVP)), "l"(kn + i*2048));
                asm volatile("cp.async.cg.shared.global [%0], [%1], 16;"
                             :: "r"(vss + boff + (uint32_t)(i*16*KVP)), "l"(vn + i*131072));
            }
            asm volatile("cp.async.commit_group;");
        }

        uint32_t kb = kaddr0 + buf*KVBUF;
        uint32_t vb = vaddr0 + buf*KVBUF;

        // ---- S = Q K^T : 4 k16-steps; b-frags shared across 2 row-blocks ----
        float s[2][8][4] = {};
        #pragma unroll
        for (int t = 0; t < 4; t++) {
            uint32_t b0[8], b1[8];
            #pragma unroll
            for (int n = 0; n < 4; n++)
                ldsm4(b0[2*n], b1[2*n], b0[2*n+1], b1[2*n+1],
                      kb + (uint32_t)(n*16*KVP) + 32u*t);
            #pragma unroll
            for (int r = 0; r < 2; r++)
                #pragma unroll
                for (int j = 0; j < 8; j++)
                    mma_f16(s[r][j], qa[t][r][0], qa[t][r][1], qa[t][r][2], qa[t][r][3],
                            b0[j], b1[j]);
        }

        // ---- p = 2^((s-2)*log2e); packed outputs ARE the O-MMA A-frags ----
        // pa[t][0]=pp0(j=2t) (row g, k-lo), pa[t][1]=pp1(j=2t) (row g+8, k-lo),
        // pa[t][2]=pp0(j=2t+1) (row g, k-hi), pa[t][3]=pp1(j=2t+1) (row g+8, k-hi)
        uint32_t pa[2][4][4];
        #pragma unroll
        for (int r = 0; r < 2; r++)
            #pragma unroll
            for (int j = 0; j < 8; j++) {
                float y0 = fmaf(s[r][j][0], L2E, -2.f*L2E);
                float y1 = fmaf(s[r][j][1], L2E, -2.f*L2E);
                float y2 = fmaf(s[r][j][2], L2E, -2.f*L2E);
                float y3 = fmaf(s[r][j][3], L2E, -2.f*L2E);
                uint32_t pp0 = exp2_f16x2(pack_f16(y0, y1));   // row g,   keys 8j+2tig..+1
                uint32_t pp1 = exp2_f16x2(pack_f16(y2, y3));   // row g+8
                int t = j >> 1, hi = (j & 1) << 1;   // even j -> slots 0,1; odd j -> slots 2,3
                pa[r][t][hi    ] = pp0;
                pa[r][t][hi + 1] = pp1;
            }

        // ---- O += P V (+ l += P 1) : 4 k16-steps; A-frags from registers ----
        #pragma unroll
        for (int t = 0; t < 4; t++) {
            uint32_t b0[8], b1[8];
            #pragma unroll
            for (int n = 0; n < 4; n++)
                ldsm4(b0[2*n], b1[2*n], b0[2*n+1], b1[2*n+1],
                      vb + (uint32_t)(n*16*KVP) + 32u*t);
            #pragma unroll
            for (int r = 0; r < 2; r++) {
                #pragma unroll
                for (int j = 0; j < 8; j++)
                    mma_f16(o[r][j], pa[r][t][0], pa[r][t][1], pa[r][t][2], pa[r][t][3],
                            b0[j], b1[j]);
                mma_f16(o9[r], pa[r][t][0], pa[r][t][1], pa[r][t][2], pa[r][t][3],
                        bone, bone);
            }
        }
    }

    // ---- epilogue: l in o9[r][0]/o9[r][2] of tig==0 lanes; broadcast ----
    float* dst = &g_att[ob][b][0][0];
    #pragma unroll
    for (int r = 0; r < 2; r++) {
        float l0 = __shfl_sync(0xffffffffu, o9[r][0], lane & ~3);
        float l1 = __shfl_sync(0xffffffffu, o9[r][2], lane & ~3);
        float il0 = 1.f / l0, il1 = 1.f / l1;
        int qb = qt*128 + qw + 16*r;
        #pragma unroll
        for (int j = 0; j < 8; j++) {
            int d0 = 8*j + 2*tig;
            dst[(d0  )*HWN + qb + g    ] = o[r][j][0]*il0;
            dst[(d0+1)*HWN + qb + g    ] = o[r][j][1]*il0;
            dst[(d0  )*HWN + qb + g + 8] = o[r][j][2]*il1;
            dst[(d0+1)*HWN + qb + g + 8] = o[r][j][3]*il1;
        }
    }
}

// ---------------------------------------------------------------------------
// Kernel 5: out 1x1 conv (tf32 mma) + bias + residual (inline GN) + concat
// ---------------------------------------------------------------------------
__global__ void __launch_bounds__(128) outproj_kernel(
        const float* __restrict__ wA, const float* __restrict__ bA,
        const float* __restrict__ wB, const float* __restrict__ bB,
        float* __restrict__ out) {
    __shared__ float Ws[64*WPAD];
    __shared__ float Xs[64*XPAD];

    int ob = blockIdx.z, b = blockIdx.y;
    int hw0 = blockIdx.x * 64;
    int tid = threadIdx.x;
    const float* W    = ob ? wB : wA;
    const float* bias = ob ? bB : bA;
    const float* X    = &g_att[ob][b][0][0];
    const float* conv = &g_conv[ob][b][0][0];

    #pragma unroll
    for (int i = 0; i < 8; i++) {
        int idx = tid + i*128;
        int row = idx >> 4, c4 = (idx & 15)*4;
        uint32_t dW = (uint32_t)__cvta_generic_to_shared(Ws + row*WPAD + c4);
        asm volatile("cp.async.cg.shared.global [%0], [%1], 16;" :: "r"(dW), "l"(W + row*64 + c4));
    }
    asm volatile("cp.async.commit_group;");
    for (int i = tid; i < 1024; i += 128) {
        int row = i >> 4, c4 = (i & 15)*4;
        float4 v = *(const float4*)&X[row*HWN + hw0 + c4];
        float4 r;
        r.x = rna(v.x); r.y = rna(v.y); r.z = rna(v.z); r.w = rna(v.w);
        *(float4*)&Xs[row*XPAD + c4] = r;
    }
    asm volatile("cp.async.wait_group 0;");
    __syncthreads();

    int w    = tid >> 5;
    int lane = tid & 31;
    int g    = lane >> 2, tig = lane & 3;
    int out0 = w * 16;

    uint32_t aw[8][4];
    #pragma unroll
    for (int t = 0; t < 8; t++) {
        aw[t][0] = __float_as_uint(rna(Ws[(out0+g  )*WPAD + 8*t + tig    ]));
        aw[t][1] = __float_as_uint(rna(Ws[(out0+g+8)*WPAD + 8*t + tig    ]));
        aw[t][2] = __float_as_uint(rna(Ws[(out0+g  )*WPAD + 8*t + tig + 4]));
        aw[t][3] = __float_as_uint(rna(Ws[(out0+g+8)*WPAD + 8*t + tig + 4]));
    }

    float s[8][4] = {};
    #pragma unroll
    for (int t = 0; t < 8; t++)
        #pragma unroll
        for (int j = 0; j < 8; j++) {
            uint32_t b0 = __float_as_uint(Xs[(8*t+tig  )*XPAD + 8*j + g]);
            uint32_t b1 = __float_as_uint(Xs[(8*t+tig+4)*XPAD + 8*j + g]);
            mma_tf32(s[j], aw[t][0], aw[t][1], aw[t][2], aw[t][3], b0, b1);
        }

    int o0 = out0 + g, o1 = out0 + g + 8;
    float bi0 = __ldg(bias + o0), bi1 = __ldg(bias + o1);
    float a0 = g_coef[ob][b][o0][0], be0 = g_coef[ob][b][o0][1];
    float a1 = g_coef[ob][b][o1][0], be1 = g_coef[ob][b][o1][1];
    float* dst = out + (b*128 + ob*64)*HWN;
    #pragma unroll
    for (int j = 0; j < 8; j++) {
        int hwj = hw0 + 8*j + 2*tig;
        float2 c0 = *(const float2*)&conv[o0*HWN + hwj];
        float2 c1 = *(const float2*)&conv[o1*HWN + hwj];
        *(float2*)&dst[o0*HWN + hwj] =
            make_float2(s[j][0] + bi0 + (a0*c0.x + be0), s[j][1] + bi0 + (a0*c0.y + be0));
        *(float2*)&dst[o1*HWN + hwj] =
            make_float2(s[j][2] + bi1 + (a1*c1.x + be1), s[j][3] + bi1 + (a1*c1.y + be1));
    }
}

// ---------------------------------------------------------------------------
extern "C" void kernel_launch(void* const* d_in, const int* in_sizes, int n_in,
                              void* d_out, int out_size) {
    const float* inputs = (const float*)d_in[0];
    const float* dw1_w  = (const float*)d_in[1];
    const float* dw1_b  = (const float*)d_in[2];
    const float* dw2_w  = (const float*)d_in[3];
    const float* dw2_b  = (const float*)d_in[4];
    const float* gnA_w  = (const float*)d_in[5];
    const float* gnA_b  = (const float*)d_in[6];
    const float* gnB_w  = (const float*)d_in[7];
    const float* gnB_b  = (const float*)d_in[8];
    const float* qkvA_w = (const float*)d_in[9];
    const float* qkvB_w = (const float*)d_in[10];
    const float* outA_w = (const float*)d_in[11];
    const float* outA_b = (const float*)d_in[12];
    const float* outB_w = (const float*)d_in[13];
    const float* outB_b = (const float*)d_in[14];
    float* out = (float*)d_out;

    cudaFuncSetAttribute(attn_kernel, cudaFuncAttributeMaxDynamicSharedMemorySize, 46080);
    cudaFuncSetAttribute(qkv_kernel,  cudaFuncAttributeMaxDynamicSharedMemorySize, 70656);

    dwconv_kernel <<<dim3(64, BN),    256>>>(inputs, dw1_w, dw1_b, dw2_w, dw2_b);
    coef_kernel   <<<1, 512>>>(gnA_w, gnA_b, gnB_w, gnB_b);
    qkv_kernel    <<<dim3(64, BN, 2), 384, 70656>>>(qkvA_w, qkvB_w);
    attn_kernel   <<<dim3(32, BN, 2), 128, 46080>>>();
    outproj_kernel<<<dim3(64, BN, 2), 128>>>(outA_w, outA_b, outB_w, outB_b, out);
}

// round 16
// speedup vs baseline: 1.4179x; 1.0300x over previous
#include <cuda_runtime.h>
#include <cuda_fp16.h>
#include <cstdint>

#define BN  4
#define C   64
#define HH  64
#define WWD 64
#define HWN 4096
#define EPSV 1e-5f

// Scratch (static device globals; no allocation at runtime)
__device__ float g_conv[2][BN][C][HWN];      // dwconv+leaky outputs
__device__ float g_stats[2][BN][C][2];       // per-channel sum, sumsq
__device__ float g_coef[2][BN][C][2];        // per-channel alpha, beta (groupnorm)
__device__ __half g_qT[2][BN][HWN][64];      // Q transposed [hw][d], pre-scaled by 0.125
__device__ __half g_kT[2][BN][HWN][64];      // K transposed [hw][d]
__device__ __half g_vb[2][BN][64][HWN];      // V [d][hw]

__device__ __forceinline__ int refl(int i, int n) {
    if (i < 0) i = -i;
    if (i >= n) i = 2*n - 2 - i;
    return i;
}

__device__ __forceinline__ float rna(float x) {
    uint32_t r;
    asm("cvt.rna.tf32.f32 %0, %1;" : "=r"(r) : "f"(x));
    return __uint_as_float(r);
}

__device__ __forceinline__ void mma_tf32(float c[4],
                                         uint32_t a0, uint32_t a1, uint32_t a2, uint32_t a3,
                                         uint32_t b0, uint32_t b1) {
    asm volatile(
        "mma.sync.aligned.m16n8k8.row.col.f32.tf32.tf32.f32 "
        "{%0,%1,%2,%3}, {%4,%5,%6,%7}, {%8,%9}, {%0,%1,%2,%3};"
        : "+f"(c[0]), "+f"(c[1]), "+f"(c[2]), "+f"(c[3])
        : "r"(a0), "r"(a1), "r"(a2), "r"(a3), "r"(b0), "r"(b1));
}

__device__ __forceinline__ void mma_f16(float c[4],
                                        uint32_t a0, uint32_t a1, uint32_t a2, uint32_t a3,
                                        uint32_t b0, uint32_t b1) {
    asm volatile(
        "mma.sync.aligned.m16n8k16.row.col.f32.f16.f16.f32 "
        "{%0,%1,%2,%3}, {%4,%5,%6,%7}, {%8,%9}, {%0,%1,%2,%3};"
        : "+f"(c[0]), "+f"(c[1]), "+f"(c[2]), "+f"(c[3])
        : "r"(a0), "r"(a1), "r"(a2), "r"(a3), "r"(b0), "r"(b1));
}

__device__ __forceinline__ void ldsm4(uint32_t& r0, uint32_t& r1, uint32_t& r2, uint32_t& r3,
                                      uint32_t addr) {
    asm volatile("ldmatrix.sync.aligned.m8n8.x4.shared.b16 {%0,%1,%2,%3}, [%4];"
                 : "=r"(r0), "=r"(r1), "=r"(r2), "=r"(r3) : "r"(addr));
}

__device__ __forceinline__ uint32_t pack_f16(float lo, float hi) {
    uint32_t r;
    asm("cvt.rn.f16x2.f32 %0, %1, %2;" : "=r"(r) : "f"(hi), "f"(lo));
    return r;
}

__device__ __forceinline__ uint32_t exp2_f16x2(uint32_t y) {
    uint32_t r;
    asm("ex2.approx.f16x2 %0, %1;" : "=r"(r) : "r"(y));
    return r;
}

// ---------------------------------------------------------------------------
// Kernel 1: depthwise conv, both branches, + per-channel stats. grid (C, BN)
// ---------------------------------------------------------------------------
__global__ void __launch_bounds__(256) dwconv_kernel(
        const float* __restrict__ inp,
        const float* __restrict__ w3, const float* __restrict__ b3,
        const float* __restrict__ w5, const float* __restrict__ b5) {
    __shared__ float t[68*68];
    int c = blockIdx.x, b = blockIdx.y;
    int tid = threadIdx.x;
    const float* src = inp + (b*C + c)*HWN;

    for (int idx = tid; idx < 68*68; idx += 256) {
        int r = idx / 68, col = idx - r*68;
        t[idx] = src[refl(r-2, HH)*WWD + refl(col-2, WWD)];
    }
    float w3r[9], w5r[25];
    #pragma unroll
    for (int k = 0; k < 9;  k++) w3r[k] = __ldg(w3 + c*9  + k);
    #pragma unroll
    for (int k = 0; k < 25; k++) w5r[k] = __ldg(w5 + c*25 + k);
    float bb3 = __ldg(b3 + c), bb5 = __ldg(b5 + c);
    __syncthreads();

    float s0 = 0.f, ss0 = 0.f, s1 = 0.f, ss1 = 0.f;
    #pragma unroll 4
    for (int k = 0; k < 16; k++) {
        int hw = tid + 256*k;
        int i = hw >> 6, j = hw & 63;
        const float* ce = &t[(i+2)*68 + (j+2)];
        float a3 = bb3;
        #pragma unroll
        for (int a = 0; a < 3; a++)
            #pragma unroll
            for (int q = 0; q < 3; q++)
                a3 += w3r[a*3+q] * ce[(a-1)*68 + (q-1)];
        float a5 = bb5;
        #pragma unroll
        for (int a = 0; a < 5; a++)
            #pragma unroll
            for (int q = 0; q < 5; q++)
                a5 += w5r[a*5+q] * ce[(a-2)*68 + (q-2)];
        float y0 = a3 > 0.f ? a3 : 0.01f*a3;
        float y1 = a5 > 0.f ? a5 : 0.01f*a5;
        g_conv[0][b][c][hw] = y0;
        g_conv[1][b][c][hw] = y1;
        s0 += y0; ss0 += y0*y0; s1 += y1; ss1 += y1*y1;
    }
    __syncthreads();
    t[tid] = s0; t[256+tid] = ss0; t[512+tid] = s1; t[768+tid] = ss1;
    __syncthreads();
    for (int st = 128; st > 0; st >>= 1) {
        if (tid < st) {
            t[tid]     += t[tid+st];     t[256+tid] += t[256+tid+st];
            t[512+tid] += t[512+tid+st]; t[768+tid] += t[768+tid+st];
        }
        __syncthreads();
    }
    if (tid == 0) {
        g_stats[0][b][c][0] = t[0];   g_stats[0][b][c][1] = t[256];
        g_stats[1][b][c][0] = t[512]; g_stats[1][b][c][1] = t[768];
    }
}

// ---------------------------------------------------------------------------
// Kernel 2: fold GroupNorm stats into per-channel alpha/beta. 1 block, 512 thr
// ---------------------------------------------------------------------------
__global__ void coef_kernel(const float* __restrict__ gwA, const float* __restrict__ gbA,
                            const float* __restrict__ gwB, const float* __restrict__ gbB) {
    int idx = threadIdx.x;
    int br = idx >> 8, b = (idx >> 6) & 3, c = idx & 63;
    int g0 = c & ~3;
    float sum = 0.f, ssum = 0.f;
    #pragma unroll
    for (int k = 0; k < 4; k++) {
        sum  += g_stats[br][b][g0+k][0];
        ssum += g_stats[br][b][g0+k][1];
    }
    float mean = sum * (1.f/16384.f);
    float var  = ssum * (1.f/16384.f) - mean*mean;
    float rs   = rsqrtf(var + EPSV);
    float gw = br ? __ldg(gwB + c) : __ldg(gwA + c);
    float gb = br ? __ldg(gbB + c) : __ldg(gbA + c);
    float alpha = rs * gw;
    g_coef[br][b][c][0] = alpha;
    g_coef[br][b][c][1] = gb - mean * alpha;
}

// ---------------------------------------------------------------------------
// Kernel 3: qkv 1x1 conv (tf32 mma), GN fused into X staging.
// Q -> g_qT fp16 [hw][d] scaled 0.125; K -> g_kT fp16 [hw][d]; V -> g_vb fp16 [d][hw]
// grid (64, BN, 2), block 384, dyn smem 70656
// ---------------------------------------------------------------------------
#define WPAD 68
#define XPAD 72

__global__ void __launch_bounds__(384) qkv_kernel(const float* __restrict__ wA,
                                                  const float* __restrict__ wB) {
    extern __shared__ float qsm[];
    float* Ws = qsm;              // [192][WPAD]
    float* Xs = qsm + 192*WPAD;   // [64][XPAD]

    int br = blockIdx.z, b = blockIdx.y;
    int hw0 = blockIdx.x * 64;
    int tid = threadIdx.x;
    const float* W  = br ? wB : wA;
    const float* Xc = &g_conv[br][b][0][0];

    #pragma unroll
    for (int i = 0; i < 8; i++) {
        int idx = tid + i*384;
        int row = idx >> 4, c4 = (idx & 15)*4;
        uint32_t d = (uint32_t)__cvta_generic_to_shared(Ws + row*WPAD + c4);
        asm volatile("cp.async.cg.shared.global [%0], [%1], 16;" :: "r"(d), "l"(W + row*64 + c4));
    }
    asm volatile("cp.async.commit_group;");
    for (int i = tid; i < 1024; i += 384) {
        int row = i >> 4, c4 = (i & 15)*4;
        float4 v = *(const float4*)&Xc[row*HWN + hw0 + c4];
        float a  = g_coef[br][b][row][0];
        float be = g_coef[br][b][row][1];
        float4 r;
        r.x = rna(a*v.x + be); r.y = rna(a*v.y + be);
        r.z = rna(a*v.z + be); r.w = rna(a*v.w + be);
        *(float4*)&Xs[row*XPAD + c4] = r;
    }
    asm volatile("cp.async.wait_group 0;");
    __syncthreads();

    int w    = tid >> 5;
    int lane = tid & 31;
    int g    = lane >> 2, tig = lane & 3;
    int out0 = w * 16;

    uint32_t aw[8][4];
    #pragma unroll
    for (int t = 0; t < 8; t++) {
        aw[t][0] = __float_as_uint(rna(Ws[(out0+g  )*WPAD + 8*t + tig    ]));
        aw[t][1] = __float_as_uint(rna(Ws[(out0+g+8)*WPAD + 8*t + tig    ]));
        aw[t][2] = __float_as_uint(rna(Ws[(out0+g  )*WPAD + 8*t + tig + 4]));
        aw[t][3] = __float_as_uint(rna(Ws[(out0+g+8)*WPAD + 8*t + tig + 4]));
    }

    float s[8][4] = {};
    #pragma unroll
    for (int t = 0; t < 8; t++)
        #pragma unroll
        for (int j = 0; j < 8; j++) {
            uint32_t b0 = __float_as_uint(Xs[(8*t+tig  )*XPAD + 8*j + g]);
            uint32_t b1 = __float_as_uint(Xs[(8*t+tig+4)*XPAD + 8*j + g]);
            mma_tf32(s[j], aw[t][0], aw[t][1], aw[t][2], aw[t][3], b0, b1);
        }

    if (out0 < 64) {                  // Q -> g_qT [hw][d] fp16, pre-scaled
        __half* qT = &g_qT[br][b][0][0];
        int o0 = out0 + g, o1 = o0 + 8;
        #pragma unroll
        for (int j = 0; j < 8; j++) {
            int hwj = hw0 + 8*j + 2*tig;
            qT[(hwj  )*64 + o0] = __float2half(s[j][0]*0.125f);
            qT[(hwj+1)*64 + o0] = __float2half(s[j][1]*0.125f);
            qT[(hwj  )*64 + o1] = __float2half(s[j][2]*0.125f);
            qT[(hwj+1)*64 + o1] = __float2half(s[j][3]*0.125f);
        }
    } else if (out0 < 128) {          // K -> g_kT [hw][d] fp16
        __half* kT = &g_kT[br][b][0][0];
        int o0 = out0 - 64 + g, o1 = o0 + 8;
        #pragma unroll
        for (int j = 0; j < 8; j++) {
            int hwj = hw0 + 8*j + 2*tig;
            kT[(hwj  )*64 + o0] = __float2half(s[j][0]);
            kT[(hwj+1)*64 + o0] = __float2half(s[j][1]);
            kT[(hwj  )*64 + o1] = __float2half(s[j][2]);
            kT[(hwj+1)*64 + o1] = __float2half(s[j][3]);
        }
    } else {                          // V -> g_vb [d][hw] fp16 packed
        int d0 = out0 - 128 + g, d1 = d0 + 8;
        #pragma unroll
        for (int j = 0; j < 8; j++) {
            int hwj = hw0 + 8*j + 2*tig;
            *(uint32_t*)&g_vb[br][b][d0][hwj] = pack_f16(s[j][0], s[j][1]);
            *(uint32_t*)&g_vb[br][b][d1][hwj] = pack_f16(s[j][2], s[j][3]);
        }
    }
}

// ---------------------------------------------------------------------------
// Kernel 4: flash attention + FUSED output projection.
// Main loop: fp16 mma + ldmatrix, warp-M=32, direct C->A reuse (R15).
// Epilogue: reuse dead KV smem; normalized O -> fp16 Xe[q][72-stride];
// W_out staged fp32; fp16 GEMM out = W*O/l + bias + GN(conv) residual -> d_out.
// Deletes g_att round-trip and the outproj kernel.
// block 128 (4 warps), grid (32, BN, 2), dyn smem 46080.
// ---------------------------------------------------------------------------
#define KVP 144   // bytes per smem row (72 halves)
#define L2E 1.4426950408889634f
#define XEP 72    // Xe row stride in halves (conflict-free: bank = 4g+tig+c)

__global__ void __launch_bounds__(128, 2) attn_kernel(
        const float* __restrict__ outA_w, const float* __restrict__ outA_b,
        const float* __restrict__ outB_w, const float* __restrict__ outB_b,
        float* __restrict__ out) {
    extern __shared__ char smc[];
    char* KTc = smc;                  // [2][64][KVP]
    char* Vc  = smc + 2*64*KVP;       // [2][64][KVP]

    int qt = blockIdx.x;
    int b  = blockIdx.y;
    int ob = blockIdx.z;
    const __half* qTg = &g_qT[ob^1][b][0][0];
    const char* kg = (const char*)&g_kT[ob][b][0][0];
    const char* vg = (const char*)&g_vb[ob][b][0][0];

    int tid  = threadIdx.x;
    int w    = tid >> 5;
    int lane = tid & 31;
    int g    = lane >> 2, tig = lane & 3;
    int qw = 32*w;

    // cp.async staging: 128 threads, 16B chunks; 4 passes cover 64 rows (128B/row)
    int row16 = tid >> 3, ch = tid & 7;
    const char* ksg = kg + row16*128  + ch*16;   // +kt*8192;  +i*2048 (16 rows)
    const char* vsg = vg + row16*8192 + ch*16;   // +kt*128;   +i*131072
    uint32_t kss = (uint32_t)__cvta_generic_to_shared(KTc) + row16*KVP + ch*16;
    uint32_t vss = (uint32_t)__cvta_generic_to_shared(Vc)  + row16*KVP + ch*16;
    const uint32_t KVBUF = 64*KVP;

    // Q A-fragments (fp16 pairs, pre-scaled): 4 k16-steps x 2 row-blocks
    uint32_t qa[4][2][4];
    #pragma unroll
    for (int r = 0; r < 2; r++) {
        int r0 = (qt*128 + qw + 16*r + g)*64;
        int r1 = r0 + 8*64;
        #pragma unroll
        for (int t = 0; t < 4; t++) {
            qa[t][r][0] = *(const uint32_t*)&qTg[r0 + 16*t + 2*tig    ];
            qa[t][r][1] = *(const uint32_t*)&qTg[r1 + 16*t + 2*tig    ];
            qa[t][r][2] = *(const uint32_t*)&qTg[r0 + 16*t + 2*tig + 8];
            qa[t][r][3] = *(const uint32_t*)&qTg[r1 + 16*t + 2*tig + 8];
        }
    }

    // ldmatrix lane addressing
    int p  = lane & 7;
    int q4 = lane >> 3;
    uint32_t rowpart = (uint32_t)((8*(q4 >> 1) + p)*KVP + 16*(q4 & 1));
    uint32_t kaddr0 = (uint32_t)__cvta_generic_to_shared(KTc) + rowpart;
    uint32_t vaddr0 = (uint32_t)__cvta_generic_to_shared(Vc)  + rowpart;

    // constant ones B-fragment for l accumulators
    uint32_t bone = (lane < 4) ? 0x3C003C00u : 0u;

    // prefetch kt=0
    #pragma unroll
    for (int i = 0; i < 4; i++) {
        asm volatile("cp.async.cg.shared.global [%0], [%1], 16;"
                     :: "r"(kss + (uint32_t)(i*16*KVP)), "l"(ksg + i*2048));
        asm volatile("cp.async.cg.shared.global [%0], [%1], 16;"
                     :: "r"(vss + (uint32_t)(i*16*KVP)), "l"(vsg + i*131072));
    }
    asm volatile("cp.async.commit_group;");

    float o[2][8][4] = {};
    float o9[2][4] = {};   // l accumulators per row-block

    for (int kt = 0; kt < 64; kt++) {
        int buf = kt & 1;
        asm volatile("cp.async.wait_group 0;");
        __syncthreads();

        if (kt + 1 < 64) {
            uint32_t boff = (buf ^ 1) * KVBUF;
            const char* kn = ksg + (kt+1)*8192;
            const char* vn = vsg + (kt+1)*128;
            #pragma unroll
            for (int i = 0; i < 4; i++) {
                asm volatile("cp.async.cg.shared.global [%0], [%1], 16;"
                             :: "r"(kss + boff + (uint32_t)(i*16*KVP)), "l"(kn + i*2048));
                asm volatile("cp.async.cg.shared.global [%0], [%1], 16;"
                             :: "r"(vss + boff + (uint32_t)(i*16*KVP)), "l"(vn + i*131072));
            }
            asm volatile("cp.async.commit_group;");
        }

        uint32_t kb = kaddr0 + buf*KVBUF;
        uint32_t vb = vaddr0 + buf*KVBUF;

        // ---- S = Q K^T : 4 k16-steps; b-frags shared across 2 row-blocks ----
        float s[2][8][4] = {};
        #pragma unroll
        for (int t = 0; t < 4; t++) {
            uint32_t b0[8], b1[8];
            #pragma unroll
            for (int n = 0; n < 4; n++)
                ldsm4(b0[2*n], b1[2*n], b0[2*n+1], b1[2*n+1],
                      kb + (uint32_t)(n*16*KVP) + 32u*t);
            #pragma unroll
            for (int r = 0; r < 2; r++)
                #pragma unroll
                for (int j = 0; j < 8; j++)
                    mma_f16(s[r][j], qa[t][r][0], qa[t][r][1], qa[t][r][2], qa[t][r][3],
                            b0[j], b1[j]);
        }

        // ---- p = 2^((s-2)*log2e); packed outputs ARE the O-MMA A-frags ----
        uint32_t pa[2][4][4];
        #pragma unroll
        for (int r = 0; r < 2; r++)
            #pragma unroll
            for (int j = 0; j < 8; j++) {
                float y0 = fmaf(s[r][j][0], L2E, -2.f*L2E);
                float y1 = fmaf(s[r][j][1], L2E, -2.f*L2E);
                float y2 = fmaf(s[r][j][2], L2E, -2.f*L2E);
                float y3 = fmaf(s[r][j][3], L2E, -2.f*L2E);
                uint32_t pp0 = exp2_f16x2(pack_f16(y0, y1));   // row g
                uint32_t pp1 = exp2_f16x2(pack_f16(y2, y3));   // row g+8
                int t = j >> 1, hi = (j & 1) << 1;
                pa[r][t][hi    ] = pp0;
                pa[r][t][hi + 1] = pp1;
            }

        // ---- O += P V (+ l += P 1) : 4 k16-steps; A-frags from registers ----
        #pragma unroll
        for (int t = 0; t < 4; t++) {
            uint32_t b0[8], b1[8];
            #pragma unroll
            for (int n = 0; n < 4; n++)
                ldsm4(b0[2*n], b1[2*n], b0[2*n+1], b1[2*n+1],
                      vb + (uint32_t)(n*16*KVP) + 32u*t);
            #pragma unroll
            for (int r = 0; r < 2; r++) {
                #pragma unroll
                for (int j = 0; j < 8; j++)
                    mma_f16(o[r][j], pa[r][t][0], pa[r][t][1], pa[r][t][2], pa[r][t][3],
                            b0[j], b1[j]);
                mma_f16(o9[r], pa[r][t][0], pa[r][t][1], pa[r][t][2], pa[r][t][3],
                        bone, bone);
            }
        }
    }

    // ======================= FUSED OUTPUT PROJECTION =======================
    __syncthreads();   // all warps done reading KV smem; safe to reuse

    float*  Wsf = (float*)smc;               // [64][WPAD] fp32 out-weights (17408B)
    __half* Xe  = (__half*)(smc + 17408);    // [128][XEP] fp16 normalized O (18432B)
    const float* Wout = ob ? outB_w : outA_w;
    const float* bias = ob ? outB_b : outA_b;

    // stage W_out via cp.async (overlaps with Xe stores)
    #pragma unroll
    for (int i = 0; i < 8; i++) {
        int idx = tid + i*128;
        int row = idx >> 4, c4 = (idx & 15)*4;
        uint32_t d = (uint32_t)__cvta_generic_to_shared(Wsf + row*WPAD + c4);
        asm volatile("cp.async.cg.shared.global [%0], [%1], 16;" :: "r"(d), "l"(Wout + row*64 + c4));
    }
    asm volatile("cp.async.commit_group;");

    // normalize O and store fp16 Xe[q_local][d] (u32 stores, conflict-free)
    #pragma unroll
    for (int r = 0; r < 2; r++) {
        float l0 = __shfl_sync(0xffffffffu, o9[r][0], lane & ~3);
        float l1 = __shfl_sync(0xffffffffu, o9[r][2], lane & ~3);
        float il0 = 1.f / l0, il1 = 1.f / l1;
        int q0 = qw + 16*r + g;
        #pragma unroll
        for (int j = 0; j < 8; j++) {
            int dcol = 8*j + 2*tig;
            *(uint32_t*)&Xe[(q0  )*XEP + dcol] = pack_f16(o[r][j][0]*il0, o[r][j][1]*il0);
            *(uint32_t*)&Xe[(q0+8)*XEP + dcol] = pack_f16(o[r][j][2]*il1, o[r][j][3]*il1);
        }
    }
    asm volatile("cp.async.wait_group 0;");
    __syncthreads();

    // out GEMM: warp w -> out channels 16w..16w+15; n = 128 q positions
    int out0 = 16*w;
    uint32_t awo[4][4];
    #pragma unroll
    for (int t = 0; t < 4; t++) {
        const float* r0 = Wsf + (out0+g  )*WPAD + 16*t + 2*tig;
        const float* r1 = Wsf + (out0+g+8)*WPAD + 16*t + 2*tig;
        awo[t][0] = pack_f16(r0[0], r0[1]);       // row g,   k-lo
        awo[t][1] = pack_f16(r1[0], r1[1]);       // row g+8, k-lo
        awo[t][2] = pack_f16(r0[8], r0[9]);       // row g,   k-hi
        awo[t][3] = pack_f16(r1[8], r1[9]);       // row g+8, k-hi
    }

    float c2[16][4] = {};
    #pragma unroll
    for (int t = 0; t < 4; t++)
        #pragma unroll
        for (int j = 0; j < 16; j++) {
            uint32_t b0 = *(const uint32_t*)&Xe[(8*j+g)*XEP + 16*t + 2*tig    ];
            uint32_t b1 = *(const uint32_t*)&Xe[(8*j+g)*XEP + 16*t + 2*tig + 8];
            mma_f16(c2[j], awo[t][0], awo[t][1], awo[t][2], awo[t][3], b0, b1);
        }

    // bias + inline-GN residual + store
    int o0 = out0 + g, o1 = o0 + 8;
    float bi0 = __ldg(bias + o0), bi1 = __ldg(bias + o1);
    float a0 = g_coef[ob][b][o0][0], be0 = g_coef[ob][b][o0][1];
    float a1 = g_coef[ob][b][o1][0], be1 = g_coef[ob][b][o1][1];
    const float* conv = &g_conv[ob][b][0][0];
    float* dst = out + (b*128 + ob*64)*HWN;
    #pragma unroll
    for (int j = 0; j < 16; j++) {
        int hwj = qt*128 + 8*j + 2*tig;
        float2 cv0 = *(const float2*)&conv[o0*HWN + hwj];
        float2 cv1 = *(const float2*)&conv[o1*HWN + hwj];
        *(float2*)&dst[o0*HWN + hwj] =
            make_float2(c2[j][0] + bi0 + (a0*cv0.x + be0), c2[j][1] + bi0 + (a0*cv0.y + be0));
        *(float2*)&dst[o1*HWN + hwj] =
            make_float2(c2[j][2] + bi1 + (a1*cv1.x + be1), c2[j][3] + bi1 + (a1*cv1.y + be1));
    }
}

// ---------------------------------------------------------------------------
extern "C" void kernel_launch(void* const* d_in, const int* in_sizes, int n_in,
                              void* d_out, int out_size) {
    const float* inputs = (const float*)d_in[0];
    const float* dw1_w  = (const float*)d_in[1];
    const float* dw1_b  = (const float*)d_in[2];
    const float* dw2_w  = (const float*)d_in[3];
    const float* dw2_b  = (const float*)d_in[4];
    const float* gnA_w  = (const float*)d_in[5];
    const float* gnA_b  = (const float*)d_in[6];
    const float* gnB_w  = (const float*)d_in[7];
    const float* gnB_b  = (const float*)d_in[8];
    const float* qkvA_w = (const float*)d_in[9];
    const float* qkvB_w = (const float*)d_in[10];
    const float* outA_w = (const float*)d_in[11];
    const float* outA_b = (const float*)d_in[12];
    const float* outB_w = (const float*)d_in[13];
    const float* outB_b = (const float*)d_in[14];
    float* out = (float*)d_out;

    cudaFuncSetAttribute(attn_kernel, cudaFuncAttributeMaxDynamicSharedMemorySize, 46080);
    cudaFuncSetAttribute(qkv_kernel,  cudaFuncAttributeMaxDynamicSharedMemorySize, 70656);

    dwconv_kernel <<<dim3(64, BN),    256>>>(inputs, dw1_w, dw1_b, dw2_w, dw2_b);
    coef_kernel   <<<1, 512>>>(gnA_w, gnA_b, gnB_w, gnB_b);
    qkv_kernel    <<<dim3(64, BN, 2), 384, 70656>>>(qkvA_w, qkvB_w);
    attn_kernel   <<<dim3(32, BN, 2), 128, 46080>>>(outA_w, outA_b, outB_w, outB_b, out);
}